// round 14
// baseline (speedup 1.0000x reference)
#include <cuda_runtime.h>
#include <math.h>

// ---------------- fixed problem shapes ----------------
#define NN   4
#define CC   1024
#define DD   768
#define HH   12
#define EE   32
#define MM   4
#define PP   256
#define RR   (NN*PP)     // 1024
#define KBL  12
#define NOUT 97

#define WSCALE     1024.0f
#define WSCALE_INV (1.0f/1024.0f)

// ---------------- scratch ----------------
__device__ float g_ent_emb[NN*EE*DD];
__device__ float g_ent_att[NN*EE*HH*CC];
__device__ float g_ht_att [NN*PP*CC];
__device__ float g_rs     [RR*DD];
__device__ float g_hs2    [RR*DD];
__device__ float g_ts2    [RR*DD];

// W_bil fragments (fp16, x1024): 3072 chunks x 13 nt x 32 lanes x uint2
__device__ __align__(16) unsigned char g_Wp[3072UL*13*32*8];
// W_head/W_tail fragments (fp16, x1024): [2][96 kc][96 nt][32] uint2
__device__ __align__(16) unsigned char g_Whtp[2UL*96*96*32*8];
// seq fragments (fp16, unscaled): [4][64 kc][96 nt][32] uint2
__device__ __align__(16) unsigned char g_seqf[4UL*64*96*32*8];

// ---------------- fp16 helpers ----------------
__device__ __forceinline__ unsigned pack_f16x2(float hi_f, float lo_f) {
    unsigned r;
    asm("cvt.rn.f16x2.f32 %0, %1, %2;" : "=r"(r) : "f"(hi_f), "f"(lo_f));
    return r;
}
// split (p0 lower, p1 upper) into f16x2 hi + f16x2 lo residual (~22-bit total)
__device__ __forceinline__ void split2h(float p0, float p1, unsigned& hi, unsigned& lo) {
    hi = pack_f16x2(p1, p0);
    float f0, f1;
    asm("{\n\t.reg .b16 h0, h1;\n\t"
        "mov.b32 {h0, h1}, %2;\n\t"
        "cvt.f32.f16 %0, h0;\n\t"
        "cvt.f32.f16 %1, h1;\n\t}"
        : "=f"(f0), "=f"(f1) : "r"(hi));
    lo = pack_f16x2(p1 - f1, p0 - f0);
}
// warp mma: D += A(f16) * B(f16), m16n8k16, row.col, fp32 accum
__device__ __forceinline__ void mma_f16(float* d, const unsigned* a,
                                        unsigned b0, unsigned b1) {
    asm volatile(
        "mma.sync.aligned.m16n8k16.row.col.f32.f16.f16.f32 "
        "{%0,%1,%2,%3}, {%4,%5,%6,%7}, {%8,%9}, {%0,%1,%2,%3};"
        : "+f"(d[0]), "+f"(d[1]), "+f"(d[2]), "+f"(d[3])
        : "r"(a[0]), "r"(a[1]), "r"(a[2]), "r"(a[3]), "r"(b0), "r"(b1));
}

// slot for k-pair p within a 16-value fragment row (hi at slot, lo at slot+2)
__device__ __forceinline__ int pair_slot(int p) {
    return (p < 4) ? 4*p : 4*(p - 4) + 1;
}

// ============================================================================
// P0: pack W_bil (x1024, fp16) into B-fragment layout. grid 3072, 128 thr
// ============================================================================
__global__ void k_wt(const float* __restrict__ Wb) {
    __shared__ float Wsm[16*104];
    int chunk = blockIdx.x;
    int tid = threadIdx.x;
    int row0 = chunk * 16;

    for (int idx = tid; idx < 16*104; idx += 128) {
        int r = idx / 104, n = idx - r*104;
        Wsm[idx] = (n < NOUT) ? Wb[(size_t)(row0 + r)*NOUT + n] * WSCALE : 0.0f;
    }
    __syncthreads();

    for (int e = tid; e < 13*32; e += 128) {
        int nt = e >> 5, lane = e & 31;
        int g = lane >> 2, t = lane & 3;
        int n = nt*8 + g, k0 = 2*t;
        unsigned b0 = pack_f16x2(Wsm[(k0 + 1)*104 + n], Wsm[(k0    )*104 + n]);
        unsigned b1 = pack_f16x2(Wsm[(k0 + 9)*104 + n], Wsm[(k0 + 8)*104 + n]);
        *(uint2*)(g_Wp + ((size_t)(chunk*13 + nt)*32 + lane)*8) = make_uint2(b0, b1);
    }
}

// ============================================================================
// P1: pack W_head / W_tail (x1024, fp16). grid (96, 2), 256 thr
// ============================================================================
__global__ void k_wht(const float* __restrict__ Wh, const float* __restrict__ Wt) {
    __shared__ float S[16*768];
    int kc = blockIdx.x;
    int w  = blockIdx.y;
    const float* W = w ? Wt : Wh;
    int tid = threadIdx.x;

    for (int idx = tid; idx < 16*768; idx += 256)
        S[idx] = W[(size_t)kc*16*768 + idx] * WSCALE;
    __syncthreads();

    for (int e = tid; e < 96*32; e += 256) {
        int nt = e >> 5, lane = e & 31;
        int g = lane >> 2, t = lane & 3;
        int n = nt*8 + g, k0 = 2*t;
        unsigned b0 = pack_f16x2(S[(k0 + 1)*768 + n], S[(k0    )*768 + n]);
        unsigned b1 = pack_f16x2(S[(k0 + 9)*768 + n], S[(k0 + 8)*768 + n]);
        *(uint2*)(g_Whtp + ((((size_t)w*96 + kc)*96 + nt)*32 + lane)*8) = make_uint2(b0, b1);
    }
}

// ============================================================================
// P2: pack seq (fp16, unscaled). grid (64, 4), 256 thr
// ============================================================================
__global__ void k_seqf(const float* __restrict__ seq) {
    __shared__ float S[16*768];
    int kc = blockIdx.x;
    int b  = blockIdx.y;
    int tid = threadIdx.x;

    for (int idx = tid; idx < 16*768; idx += 256)
        S[idx] = seq[((size_t)b*CC + kc*16)*768 + idx];
    __syncthreads();

    for (int e = tid; e < 96*32; e += 256) {
        int nt = e >> 5, lane = e & 31;
        int g = lane >> 2, t = lane & 3;
        int n = nt*8 + g, k0 = 2*t;
        unsigned b0 = pack_f16x2(S[(k0 + 1)*768 + n], S[(k0    )*768 + n]);
        unsigned b1 = pack_f16x2(S[(k0 + 9)*768 + n], S[(k0 + 8)*768 + n]);
        *(uint2*)(g_seqf + ((((size_t)b*64 + kc)*96 + nt)*32 + lane)*8) = make_uint2(b0, b1);
    }
}

// ============================================================================
// K1: entity embeddings = logsumexp over M mentions. grid (128, 2)
// ============================================================================
__global__ void k_ent_emb(const float* __restrict__ seq,
                          const int*   __restrict__ mpos) {
    int be = blockIdx.x;
    int half = blockIdx.y;
    int b  = be / EE;
    const int* mp = mpos + be*MM;
    int p0 = mp[0], p1 = mp[1], p2 = mp[2], p3 = mp[3];
    const float* sb = seq + (long)b*CC*DD;
    int d0 = half*(DD/2), d1 = d0 + DD/2;
    for (int dd = d0 + threadIdx.x; dd < d1; dd += blockDim.x) {
        float v0 = sb[p0*DD+dd], v1 = sb[p1*DD+dd];
        float v2 = sb[p2*DD+dd], v3 = sb[p3*DD+dd];
        float mx = fmaxf(fmaxf(v0, v1), fmaxf(v2, v3));
        float s  = expf(v0-mx) + expf(v1-mx) + expf(v2-mx) + expf(v3-mx);
        g_ent_emb[be*DD + dd] = mx + logf(s);
    }
}

// ============================================================================
// K2: entity attention = mean over M mention attention rows
// ============================================================================
__global__ void k_ent_att(const float* __restrict__ att,
                          const int*   __restrict__ mpos) {
    int id = blockIdx.x;
    int hd = id % HH;
    int be = id / HH;
    int b  = be / EE;
    const int* mp = mpos + be*MM;
    const float* ab = att + (long)(b*HH + hd)*CC*CC;
    float* ob = g_ent_att + (long)id*CC;
    int q0 = mp[0]*CC, q1 = mp[1]*CC, q2 = mp[2]*CC, q3 = mp[3]*CC;
    for (int c = threadIdx.x; c < CC; c += blockDim.x) {
        float s = ab[q0+c] + ab[q1+c] + ab[q2+c] + ab[q3+c];
        ob[c] = s * 0.25f;
    }
}

// ============================================================================
// K3: ht_att = mean_h(h_att * t_att), row-normalized
// ============================================================================
__global__ void k_ht_att(const int* __restrict__ hts) {
    int bp = blockIdx.x;
    int b  = bp / PP;
    int eh = hts[bp*2 + 0];
    int et = hts[bp*2 + 1];
    const float* ah = g_ent_att + (long)(b*EE + eh)*HH*CC;
    const float* at = g_ent_att + (long)(b*EE + et)*HH*CC;

    float v[4];
    float lsum = 0.f;
    #pragma unroll
    for (int q = 0; q < 4; q++) {
        int c = q*256 + threadIdx.x;
        float s = 0.f;
        #pragma unroll
        for (int hd = 0; hd < HH; hd++)
            s += ah[hd*CC + c] * at[hd*CC + c];
        s *= (1.0f / HH);
        v[q] = s;
        lsum += s;
    }
    __shared__ float red[256];
    red[threadIdx.x] = lsum;
    __syncthreads();
    for (int st = 128; st > 0; st >>= 1) {
        if (threadIdx.x < st) red[threadIdx.x] += red[threadIdx.x + st];
        __syncthreads();
    }
    float inv = 1.0f / (red[0] + 1e-30f);
    #pragma unroll
    for (int q = 0; q < 4; q++) {
        int c = q*256 + threadIdx.x;
        g_ht_att[(long)bp*CC + c] = v[q] * inv;
    }
}

// ============================================================================
// K4: rs = ht_att @ seq, fp16 2-term mma, K-SPLIT x2, 16-row tiles.
// grid (12, 64) = 768 CTAs, 256 thr: warps 0-3 K[0:512), 4-7 K[512:1024).
// ============================================================================
#define APITCH 20
__global__ void __launch_bounds__(256) k_rs_mma() {
    __shared__ __align__(16) unsigned As[2][2][16*APITCH];
    __shared__ __align__(16) float Xch[128*8];

    int ntg0 = blockIdx.x * 8;
    int r0   = blockIdx.y * 16;
    int b    = r0 >> 8;
    int tid = threadIdx.x;
    int kh  = tid >> 7;            // K-half
    int st  = tid & 127;
    int wid = st >> 5, lane = st & 31;
    int g = lane >> 2, t = lane & 3;
    int arow = st >> 3, oct = st & 7;
    int slot = pair_slot(oct);

    const float* Apt = g_ht_att + (size_t)(r0 + arow)*CC + kh*512 + oct*2;
    const size_t KSTR = (size_t)96*256;
    const char* Bp0 = (const char*)g_seqf + (((size_t)b*64*96) + ntg0 + wid*2    )*256 + lane*8 + (size_t)(kh*32)*KSTR;
    const char* Bp1 = (const char*)g_seqf + (((size_t)b*64*96) + ntg0 + wid*2 + 1)*256 + lane*8 + (size_t)(kh*32)*KSTR;

    unsigned (*A)[16*APITCH] = As[kh];

    float2 pa = *(const float2*)(Apt);
    pa.x *= WSCALE; pa.y *= WSCALE;
    uint2 bc0 = *(const uint2*)(Bp0);
    uint2 bc1 = *(const uint2*)(Bp1);
    {
        unsigned hi, lo;
        split2h(pa.x, pa.y, hi, lo);
        A[0][arow*APITCH + slot] = hi;
        A[0][arow*APITCH + slot + 2] = lo;
    }
    __syncthreads();

    float acc[2][4];
    #pragma unroll
    for (int n = 0; n < 2; n++)
        #pragma unroll
        for (int c = 0; c < 4; c++) acc[n][c] = 0.0f;

    const int NKH = 32;
    uint2 pb0, pb1;
    for (int ks = 0; ks < NKH; ks++) {
        int s = ks & 1;
        if (ks + 1 < NKH) {
            pa = *(const float2*)(Apt + (ks + 1)*16);
            pa.x *= WSCALE; pa.y *= WSCALE;
            pb0 = *(const uint2*)(Bp0 + (size_t)(ks + 1)*KSTR);
            pb1 = *(const uint2*)(Bp1 + (size_t)(ks + 1)*KSTR);
        }

        {
            uint4 ua = *(const uint4*)&A[s][g*APITCH + 4*t];
            uint4 ub = *(const uint4*)&A[s][(g + 8)*APITCH + 4*t];
            unsigned ahi[4] = {ua.x, ub.x, ua.y, ub.y};
            unsigned alo[4] = {ua.z, ub.z, ua.w, ub.w};
            mma_f16(acc[0], ahi, bc0.x, bc0.y);
            mma_f16(acc[0], alo, bc0.x, bc0.y);
            mma_f16(acc[1], ahi, bc1.x, bc1.y);
            mma_f16(acc[1], alo, bc1.x, bc1.y);
        }

        if (ks + 1 < NKH) {
            unsigned hi, lo;
            split2h(pa.x, pa.y, hi, lo);
            A[s^1][arow*APITCH + slot] = hi;
            A[s^1][arow*APITCH + slot + 2] = lo;
            bc0 = pb0; bc1 = pb1;
        }
        __syncthreads();
    }

    // combine halves
    if (kh == 1) {
        *(float4*)&Xch[st*8    ] = make_float4(acc[0][0], acc[0][1], acc[0][2], acc[0][3]);
        *(float4*)&Xch[st*8 + 4] = make_float4(acc[1][0], acc[1][1], acc[1][2], acc[1][3]);
    }
    __syncthreads();
    if (kh == 0) {
        #pragma unroll
        for (int nt = 0; nt < 2; nt++) {
            float4 o = *(const float4*)&Xch[st*8 + nt*4];
            int n0 = (ntg0 + wid*2 + nt)*8 + 2*t;
            int ra = r0 + g;
            *(float2*)(g_rs + (size_t)ra*DD + n0) =
                make_float2((acc[nt][0] + o.x)*WSCALE_INV, (acc[nt][1] + o.y)*WSCALE_INV);
            *(float2*)(g_rs + (size_t)(ra+8)*DD + n0) =
                make_float2((acc[nt][2] + o.z)*WSCALE_INV, (acc[nt][3] + o.w)*WSCALE_INV);
        }
    }
}

// ============================================================================
// K5: hs2/ts2 = tanh(concat(ent_emb[ent], rs) @ W + b), K-SPLIT x2, 16-row
// tiles. grid (12, 64, 2) = 1536 CTAs, 256 thr.
// ============================================================================
__global__ void __launch_bounds__(256) k_ht_mma(const float* __restrict__ bh,
                                                const float* __restrict__ bt,
                                                const int* __restrict__ hts) {
    __shared__ __align__(16) unsigned As[2][2][16*APITCH];
    __shared__ __align__(16) float Xch[128*8];
    __shared__ int eOff[16];

    int ntg0 = blockIdx.x * 8;
    int r0   = blockIdx.y * 16;
    int col  = blockIdx.z;
    const float* bias = col ? bt : bh;
    float* outm = col ? g_ts2 : g_hs2;

    int tid = threadIdx.x;
    int kh  = tid >> 7;
    int st  = tid & 127;
    int wid = st >> 5, lane = st & 31;
    int g = lane >> 2, t = lane & 3;
    int arow = st >> 3, oct = st & 7;
    int slot = pair_slot(oct);

    if (tid < 16) {
        int r = r0 + tid;
        eOff[tid] = ((r >> 8)*EE + hts[r*2 + col])*DD;
    }
    __syncthreads();

    const float* Apt = (kh == 0)
        ? (g_ent_emb + eOff[arow] + oct*2)
        : (g_rs + (size_t)(r0 + arow)*DD + oct*2);

    const size_t KSTR = (size_t)96*256;
    const char* Bp0 = (const char*)g_Whtp + (((size_t)col*96*96) + ntg0 + wid*2    )*256 + lane*8 + (size_t)(kh*48)*KSTR;
    const char* Bp1 = (const char*)g_Whtp + (((size_t)col*96*96) + ntg0 + wid*2 + 1)*256 + lane*8 + (size_t)(kh*48)*KSTR;

    unsigned (*A)[16*APITCH] = As[kh];

    float2 pa = *(const float2*)(Apt);
    uint2 bc0 = *(const uint2*)(Bp0);
    uint2 bc1 = *(const uint2*)(Bp1);
    {
        unsigned hi, lo;
        split2h(pa.x, pa.y, hi, lo);
        A[0][arow*APITCH + slot] = hi;
        A[0][arow*APITCH + slot + 2] = lo;
    }
    __syncthreads();

    float acc[2][4];
    #pragma unroll
    for (int n = 0; n < 2; n++)
        #pragma unroll
        for (int c = 0; c < 4; c++) acc[n][c] = 0.0f;

    const int NKH = 48;
    uint2 pb0, pb1;
    for (int ks = 0; ks < NKH; ks++) {
        int s = ks & 1;
        if (ks + 1 < NKH) {
            pa = *(const float2*)(Apt + (ks + 1)*16);
            pb0 = *(const uint2*)(Bp0 + (size_t)(ks + 1)*KSTR);
            pb1 = *(const uint2*)(Bp1 + (size_t)(ks + 1)*KSTR);
        }

        {
            uint4 ua = *(const uint4*)&A[s][g*APITCH + 4*t];
            uint4 ub = *(const uint4*)&A[s][(g + 8)*APITCH + 4*t];
            unsigned ahi[4] = {ua.x, ub.x, ua.y, ub.y};
            unsigned alo[4] = {ua.z, ub.z, ua.w, ub.w};
            mma_f16(acc[0], ahi, bc0.x, bc0.y);
            mma_f16(acc[0], alo, bc0.x, bc0.y);
            mma_f16(acc[1], ahi, bc1.x, bc1.y);
            mma_f16(acc[1], alo, bc1.x, bc1.y);
        }

        if (ks + 1 < NKH) {
            unsigned hi, lo;
            split2h(pa.x, pa.y, hi, lo);
            A[s^1][arow*APITCH + slot] = hi;
            A[s^1][arow*APITCH + slot + 2] = lo;
            bc0 = pb0; bc1 = pb1;
        }
        __syncthreads();
    }

    if (kh == 1) {
        *(float4*)&Xch[st*8    ] = make_float4(acc[0][0], acc[0][1], acc[0][2], acc[0][3]);
        *(float4*)&Xch[st*8 + 4] = make_float4(acc[1][0], acc[1][1], acc[1][2], acc[1][3]);
    }
    __syncthreads();
    if (kh == 0) {
        #pragma unroll
        for (int nt = 0; nt < 2; nt++) {
            float4 o = *(const float4*)&Xch[st*8 + nt*4];
            int n0 = (ntg0 + wid*2 + nt)*8 + 2*t;
            int ra = r0 + g;
            float b0v = bias[n0], b1v = bias[n0 + 1];
            *(float2*)(outm + (size_t)ra*DD + n0) =
                make_float2(tanhf((acc[nt][0] + o.x)*WSCALE_INV + b0v),
                            tanhf((acc[nt][1] + o.y)*WSCALE_INV + b1v));
            *(float2*)(outm + (size_t)(ra+8)*DD + n0) =
                make_float2(tanhf((acc[nt][2] + o.z)*WSCALE_INV + b0v),
                            tanhf((acc[nt][3] + o.w)*WSCALE_INV + b1v));
        }
    }
}

// ============================================================================
// K6: init output with bias
// ============================================================================
__global__ void k_init_out(const float* __restrict__ b_bil, float* __restrict__ out) {
    int i = blockIdx.x*256 + threadIdx.x;
    if (i < RR*NOUT) out[i] = b_bil[i % NOUT];
}

// ============================================================================
// K7: bilinear via fp16 single-term A mma (unchanged).
// grid (48, 16) = 768 CTAs, 128 thr, 64-row r-tiles.
// ============================================================================
#define TS_OFF  0
#define HS_OFF  16896                       // 64*66*4
#define WB_OFF  (HS_OFF + 64*17*4)          // 21248
#define CHUNK_BYTES 3328                    // 13 nt * 32 lanes * 8B
#define BIL_SMEM (WB_OFF + 2*CHUNK_BYTES)   // 27904

__global__ void __launch_bounds__(128) k_bil_mma(float* __restrict__ out) {
    extern __shared__ __align__(16) char smem[];
    float* tsS = (float*)(smem + TS_OFF);   // [64 r][66]
    float* hsS = (float*)(smem + HS_OFF);   // [64 r][17]
    char*  Wbuf = smem + WB_OFF;

    const int kb = blockIdx.x >> 2;
    const int qt = blockIdx.x & 3;
    const int r0 = blockIdx.y * 64;
    const int tid  = threadIdx.x;
    const int wid  = tid >> 5;
    const int lane = tid & 31;
    const int g = lane >> 2, t = lane & 3;

    for (int idx = tid; idx < 64*64; idx += 128) {
        int rr = idx >> 6, j = idx & 63;
        tsS[rr*66 + j] = g_ts2[(size_t)(r0 + rr)*DD + kb*64 + j];
    }
    for (int idx = tid; idx < 64*16; idx += 128) {
        int rr = idx >> 4, ii = idx & 15;
        hsS[rr*17 + ii] = g_hs2[(size_t)(r0 + rr)*DD + kb*64 + qt*16 + ii];
    }
    const size_t chunk0 = (size_t)(kb*256 + qt*64);
    {
        const char* src = (const char*)g_Wp + chunk0*CHUNK_BYTES;
        for (int e = tid; e < 416; e += 128)
            *(uint2*)(Wbuf + e*8) = *(const uint2*)(src + e*8);
    }
    __syncthreads();

    float acc[13][4];
    #pragma unroll
    for (int n = 0; n < 13; n++)
        #pragma unroll
        for (int c = 0; c < 4; c++) acc[n][c] = 0.0f;

    for (int cc = 0; cc < 64; cc++) {
        int s = cc & 1;
        uint2 pw0, pw1, pw2, pw3;
        if (cc + 1 < 64) {
            const char* src = (const char*)g_Wp + (chunk0 + cc + 1)*CHUNK_BYTES;
            pw0 = *(const uint2*)(src + (tid      )*8);
            pw1 = *(const uint2*)(src + (tid + 128)*8);
            pw2 = *(const uint2*)(src + (tid + 256)*8);
            if (tid < 32) pw3 = *(const uint2*)(src + (tid + 384)*8);
        }

        int i_loc = cc >> 2;
        int j0    = (cc & 3) * 16;
        unsigned a[4];
        {
            int ra = wid*16 + g, rb = ra + 8;
            float hA = hsS[ra*17 + i_loc];
            float hB = hsS[rb*17 + i_loc];
            float2 tA0 = *(const float2*)&tsS[ra*66 + j0 + 2*t];
            float2 tA1 = *(const float2*)&tsS[ra*66 + j0 + 2*t + 8];
            float2 tB0 = *(const float2*)&tsS[rb*66 + j0 + 2*t];
            float2 tB1 = *(const float2*)&tsS[rb*66 + j0 + 2*t + 8];
            a[0] = pack_f16x2(hA*tA0.y, hA*tA0.x);
            a[1] = pack_f16x2(hB*tB0.y, hB*tB0.x);
            a[2] = pack_f16x2(hA*tA1.y, hA*tA1.x);
            a[3] = pack_f16x2(hB*tB1.y, hB*tB1.x);
        }

        #pragma unroll
        for (int nt = 0; nt < 13; nt++) {
            uint2 w = *(const uint2*)(Wbuf + s*CHUNK_BYTES + (nt*32 + lane)*8);
            mma_f16(acc[nt], a, w.x, w.y);
        }

        __syncthreads();
        if (cc + 1 < 64) {
            char* dst = Wbuf + (s^1)*CHUNK_BYTES;
            *(uint2*)(dst + (tid      )*8) = pw0;
            *(uint2*)(dst + (tid + 128)*8) = pw1;
            *(uint2*)(dst + (tid + 256)*8) = pw2;
            if (tid < 32) *(uint2*)(dst + (tid + 384)*8) = pw3;
        }
        __syncthreads();
    }

    {
        int r1 = r0 + wid*16 + g;
        #pragma unroll
        for (int nt = 0; nt < 13; nt++) {
            int n0 = nt*8 + 2*t;
            const float* av = acc[nt];
            if (n0 < NOUT) {
                atomicAdd(&out[(size_t)r1*NOUT + n0],     av[0]*WSCALE_INV);
                atomicAdd(&out[(size_t)(r1+8)*NOUT + n0], av[2]*WSCALE_INV);
            }
            if (n0 + 1 < NOUT) {
                atomicAdd(&out[(size_t)r1*NOUT + n0 + 1],     av[1]*WSCALE_INV);
                atomicAdd(&out[(size_t)(r1+8)*NOUT + n0 + 1], av[3]*WSCALE_INV);
            }
        }
    }
}

// ============================================================================
// launch: multi-stream DAG; k_rs_mma kept as 4th launch for profiling.
// ============================================================================
extern "C" void kernel_launch(void* const* d_in, const int* in_sizes, int n_in,
                              void* d_out, int out_size) {
    const float* seq    = (const float*)d_in[0];
    const float* att    = (const float*)d_in[1];
    const int*   mpos   = (const int*  )d_in[2];
    const int*   hts    = (const int*  )d_in[3];
    const float* W_head = (const float*)d_in[4];
    const float* b_head = (const float*)d_in[5];
    const float* W_tail = (const float*)d_in[6];
    const float* b_tail = (const float*)d_in[7];
    const float* W_bil  = (const float*)d_in[8];
    const float* b_bil  = (const float*)d_in[9];
    float* out = (float*)d_out;

    static cudaStream_t s1, s2, s3;
    static cudaEvent_t evRoot, evA, evB, evC, evD, evF;
    static int inited = 0;
    if (!inited) {
        cudaStreamCreateWithFlags(&s1, cudaStreamNonBlocking);
        cudaStreamCreateWithFlags(&s2, cudaStreamNonBlocking);
        cudaStreamCreateWithFlags(&s3, cudaStreamNonBlocking);
        cudaEventCreateWithFlags(&evRoot, cudaEventDisableTiming);
        cudaEventCreateWithFlags(&evA, cudaEventDisableTiming);
        cudaEventCreateWithFlags(&evB, cudaEventDisableTiming);
        cudaEventCreateWithFlags(&evC, cudaEventDisableTiming);
        cudaEventCreateWithFlags(&evD, cudaEventDisableTiming);
        cudaEventCreateWithFlags(&evF, cudaEventDisableTiming);
        cudaFuncSetAttribute(k_bil_mma, cudaFuncAttributeMaxDynamicSharedMemorySize, BIL_SMEM);
        inited = 1;
    }

    cudaEventRecord(evRoot, 0);
    cudaStreamWaitEvent(s1, evRoot, 0);
    cudaStreamWaitEvent(s2, evRoot, 0);
    cudaStreamWaitEvent(s3, evRoot, 0);

    k_ent_att<<<NN*EE*HH, 256>>>(att, mpos);                    // 1 (main)
    k_ht_att<<<NN*PP, 256>>>(hts);                              // 2 (main)
    k_seqf<<<dim3(64, 4), 256, 0, s2>>>(seq);                   // 3 (s2)
    cudaEventRecord(evC, s2);
    cudaStreamWaitEvent(0, evC, 0);
    k_rs_mma<<<dim3(12, 64), 256>>>();                          // 4 (main) <- profiled
    k_wht<<<dim3(96, 2), 256, 0, s2>>>(W_head, W_tail);         // 5 (s2)
    cudaEventRecord(evB, s2);
    k_ent_emb<<<dim3(NN*EE, 2), 256, 0, s3>>>(seq, mpos);       // 6 (s3)
    cudaEventRecord(evD, s3);
    cudaStreamWaitEvent(0, evB, 0);
    cudaStreamWaitEvent(0, evD, 0);
    k_ht_mma<<<dim3(12, 64, 2), 256>>>(b_head, b_tail, hts);    // 7 (main)
    k_wt<<<3072, 128, 0, s1>>>(W_bil);                          // 8 (s1, runs early)
    cudaEventRecord(evA, s1);
    k_init_out<<<(RR*NOUT + 255)/256, 256, 0, s3>>>(b_bil, out);// 9 (s3)
    cudaEventRecord(evF, s3);
    cudaStreamWaitEvent(0, evA, 0);
    cudaStreamWaitEvent(0, evF, 0);
    k_bil_mma<<<dim3(KBL*4, RR/64), 128, BIL_SMEM>>>(out);      // 10 (main)
}

// round 15
// speedup vs baseline: 1.1655x; 1.1655x over previous
#include <cuda_runtime.h>
#include <math.h>

// ---------------- fixed problem shapes ----------------
#define NN   4
#define CC   1024
#define DD   768
#define HH   12
#define EE   32
#define MM   4
#define PP   256
#define RR   (NN*PP)     // 1024
#define KBL  12
#define NOUT 97

#define WSCALE     1024.0f
#define WSCALE_INV (1.0f/1024.0f)

// ---------------- scratch ----------------
__device__ float g_ent_emb[NN*EE*DD];
__device__ float g_ent_att[NN*EE*HH*CC];
__device__ float g_ht_att [NN*PP*CC];
__device__ float g_rs     [RR*DD];
__device__ float g_hs2    [RR*DD];
__device__ float g_ts2    [RR*DD];
__device__ float g_y1     [2*NN*EE*DD];   // ent_emb @ W_top per col

// W_bil fragments (fp16, x1024): 3072 chunks x 13 nt x 32 lanes x uint2
__device__ __align__(16) unsigned char g_Wp[3072UL*13*32*8];
// W_head/W_tail fragments (fp16, x1024): [2][96 kc][96 nt][32] uint2
__device__ __align__(16) unsigned char g_Whtp[2UL*96*96*32*8];
// seq fragments (fp16, unscaled): [4][64 kc][96 nt][32] uint2
__device__ __align__(16) unsigned char g_seqf[4UL*64*96*32*8];

// ---------------- fp16 helpers ----------------
__device__ __forceinline__ unsigned pack_f16x2(float hi_f, float lo_f) {
    unsigned r;
    asm("cvt.rn.f16x2.f32 %0, %1, %2;" : "=r"(r) : "f"(hi_f), "f"(lo_f));
    return r;
}
__device__ __forceinline__ void split2h(float p0, float p1, unsigned& hi, unsigned& lo) {
    hi = pack_f16x2(p1, p0);
    float f0, f1;
    asm("{\n\t.reg .b16 h0, h1;\n\t"
        "mov.b32 {h0, h1}, %2;\n\t"
        "cvt.f32.f16 %0, h0;\n\t"
        "cvt.f32.f16 %1, h1;\n\t}"
        : "=f"(f0), "=f"(f1) : "r"(hi));
    lo = pack_f16x2(p1 - f1, p0 - f0);
}
__device__ __forceinline__ void mma_f16(float* d, const unsigned* a,
                                        unsigned b0, unsigned b1) {
    asm volatile(
        "mma.sync.aligned.m16n8k16.row.col.f32.f16.f16.f32 "
        "{%0,%1,%2,%3}, {%4,%5,%6,%7}, {%8,%9}, {%0,%1,%2,%3};"
        : "+f"(d[0]), "+f"(d[1]), "+f"(d[2]), "+f"(d[3])
        : "r"(a[0]), "r"(a[1]), "r"(a[2]), "r"(a[3]), "r"(b0), "r"(b1));
}
// stage one float4 (pairs p0=2*quad, p0+1) into packed fragment row.
__device__ __forceinline__ void stage_pairs(unsigned* dst_row, int quad, float4 v) {
    unsigned hi0, lo0, hi1, lo1;
    split2h(v.x, v.y, hi0, lo0);
    split2h(v.z, v.w, hi1, lo1);
    int p0 = quad*2, p1 = p0 + 1;
    int s0 = (p0 < 4) ? 4*p0 : 4*(p0 - 4) + 1;
    int s1 = (p1 < 4) ? 4*p1 : 4*(p1 - 4) + 1;
    dst_row[s0] = hi0; dst_row[s0 + 2] = lo0;
    dst_row[s1] = hi1; dst_row[s1 + 2] = lo1;
}

// ============================================================================
// P0: pack W_bil. grid 3072, 128 thr
// ============================================================================
__global__ void k_wt(const float* __restrict__ Wb) {
    __shared__ float Wsm[16*104];
    int chunk = blockIdx.x;
    int tid = threadIdx.x;
    int row0 = chunk * 16;

    for (int idx = tid; idx < 16*104; idx += 128) {
        int r = idx / 104, n = idx - r*104;
        Wsm[idx] = (n < NOUT) ? Wb[(size_t)(row0 + r)*NOUT + n] * WSCALE : 0.0f;
    }
    __syncthreads();

    for (int e = tid; e < 13*32; e += 128) {
        int nt = e >> 5, lane = e & 31;
        int g = lane >> 2, t = lane & 3;
        int n = nt*8 + g, k0 = 2*t;
        unsigned b0 = pack_f16x2(Wsm[(k0 + 1)*104 + n], Wsm[(k0    )*104 + n]);
        unsigned b1 = pack_f16x2(Wsm[(k0 + 9)*104 + n], Wsm[(k0 + 8)*104 + n]);
        *(uint2*)(g_Wp + ((size_t)(chunk*13 + nt)*32 + lane)*8) = make_uint2(b0, b1);
    }
}

// ============================================================================
// P1: pack W_head / W_tail. grid (96, 2), 256 thr
// ============================================================================
__global__ void k_wht(const float* __restrict__ Wh, const float* __restrict__ Wt) {
    __shared__ float S[16*768];
    int kc = blockIdx.x;
    int w  = blockIdx.y;
    const float* W = w ? Wt : Wh;
    int tid = threadIdx.x;

    for (int idx = tid; idx < 16*768; idx += 256)
        S[idx] = W[(size_t)kc*16*768 + idx] * WSCALE;
    __syncthreads();

    for (int e = tid; e < 96*32; e += 256) {
        int nt = e >> 5, lane = e & 31;
        int g = lane >> 2, t = lane & 3;
        int n = nt*8 + g, k0 = 2*t;
        unsigned b0 = pack_f16x2(S[(k0 + 1)*768 + n], S[(k0    )*768 + n]);
        unsigned b1 = pack_f16x2(S[(k0 + 9)*768 + n], S[(k0 + 8)*768 + n]);
        *(uint2*)(g_Whtp + ((((size_t)w*96 + kc)*96 + nt)*32 + lane)*8) = make_uint2(b0, b1);
    }
}

// ============================================================================
// P2: pack seq. grid (64, 4), 256 thr
// ============================================================================
__global__ void k_seqf(const float* __restrict__ seq) {
    __shared__ float S[16*768];
    int kc = blockIdx.x;
    int b  = blockIdx.y;
    int tid = threadIdx.x;

    for (int idx = tid; idx < 16*768; idx += 256)
        S[idx] = seq[((size_t)b*CC + kc*16)*768 + idx];
    __syncthreads();

    for (int e = tid; e < 96*32; e += 256) {
        int nt = e >> 5, lane = e & 31;
        int g = lane >> 2, t = lane & 3;
        int n = nt*8 + g, k0 = 2*t;
        unsigned b0 = pack_f16x2(S[(k0 + 1)*768 + n], S[(k0    )*768 + n]);
        unsigned b1 = pack_f16x2(S[(k0 + 9)*768 + n], S[(k0 + 8)*768 + n]);
        *(uint2*)(g_seqf + ((((size_t)b*64 + kc)*96 + nt)*32 + lane)*8) = make_uint2(b0, b1);
    }
}

// ============================================================================
// K1: entity embeddings = logsumexp. grid (128, 2)
// ============================================================================
__global__ void k_ent_emb(const float* __restrict__ seq,
                          const int*   __restrict__ mpos) {
    int be = blockIdx.x;
    int half = blockIdx.y;
    int b  = be / EE;
    const int* mp = mpos + be*MM;
    int p0 = mp[0], p1 = mp[1], p2 = mp[2], p3 = mp[3];
    const float* sb = seq + (long)b*CC*DD;
    int d0 = half*(DD/2), d1 = d0 + DD/2;
    for (int dd = d0 + threadIdx.x; dd < d1; dd += blockDim.x) {
        float v0 = sb[p0*DD+dd], v1 = sb[p1*DD+dd];
        float v2 = sb[p2*DD+dd], v3 = sb[p3*DD+dd];
        float mx = fmaxf(fmaxf(v0, v1), fmaxf(v2, v3));
        float s  = expf(v0-mx) + expf(v1-mx) + expf(v2-mx) + expf(v3-mx);
        g_ent_emb[be*DD + dd] = mx + logf(s);
    }
}

// ============================================================================
// K2: entity attention = mean over mention attention rows
// ============================================================================
__global__ void k_ent_att(const float* __restrict__ att,
                          const int*   __restrict__ mpos) {
    int id = blockIdx.x;
    int hd = id % HH;
    int be = id / HH;
    int b  = be / EE;
    const int* mp = mpos + be*MM;
    const float* ab = att + (long)(b*HH + hd)*CC*CC;
    float* ob = g_ent_att + (long)id*CC;
    int q0 = mp[0]*CC, q1 = mp[1]*CC, q2 = mp[2]*CC, q3 = mp[3]*CC;
    for (int c = threadIdx.x; c < CC; c += blockDim.x) {
        float s = ab[q0+c] + ab[q1+c] + ab[q2+c] + ab[q3+c];
        ob[c] = s * 0.25f;
    }
}

// ============================================================================
// K3: ht_att = mean_h(h_att * t_att), row-normalized
// ============================================================================
__global__ void k_ht_att(const int* __restrict__ hts) {
    int bp = blockIdx.x;
    int b  = bp / PP;
    int eh = hts[bp*2 + 0];
    int et = hts[bp*2 + 1];
    const float* ah = g_ent_att + (long)(b*EE + eh)*HH*CC;
    const float* at = g_ent_att + (long)(b*EE + et)*HH*CC;

    float v[4];
    float lsum = 0.f;
    #pragma unroll
    for (int q = 0; q < 4; q++) {
        int c = q*256 + threadIdx.x;
        float s = 0.f;
        #pragma unroll
        for (int hd = 0; hd < HH; hd++)
            s += ah[hd*CC + c] * at[hd*CC + c];
        s *= (1.0f / HH);
        v[q] = s;
        lsum += s;
    }
    __shared__ float red[256];
    red[threadIdx.x] = lsum;
    __syncthreads();
    for (int st = 128; st > 0; st >>= 1) {
        if (threadIdx.x < st) red[threadIdx.x] += red[threadIdx.x + st];
        __syncthreads();
    }
    float inv = 1.0f / (red[0] + 1e-30f);
    #pragma unroll
    for (int q = 0; q < 4; q++) {
        int c = q*256 + threadIdx.x;
        g_ht_att[(long)bp*CC + c] = v[q] * inv;
    }
}

// ============================================================================
// K4: rs = ht_att @ seq, fp16 2-term mma, K-SPLIT x2, 32-row tiles (R13 best).
// grid (12, 32), 256 thr.
// ============================================================================
#define APITCH 20
__global__ void __launch_bounds__(256) k_rs_mma() {
    __shared__ __align__(16) unsigned As[2][2][32*APITCH];
    __shared__ __align__(16) float Xch[128*16];

    int ntg0 = blockIdx.x * 8;
    int r0   = blockIdx.y * 32;
    int b    = r0 >> 8;
    int tid = threadIdx.x;
    int kh  = tid >> 7;
    int st  = tid & 127;
    int wid = st >> 5, lane = st & 31;
    int g = lane >> 2, t = lane & 3;
    int arow = st >> 2, quad = st & 3;

    const float* Arow = g_ht_att + (size_t)(r0 + arow)*CC + kh*512 + quad*4;
    const size_t KSTR = (size_t)96*256;
    const char* Bp0 = (const char*)g_seqf + (((size_t)b*64*96) + ntg0 + wid*2    )*256 + lane*8 + (size_t)(kh*32)*KSTR;
    const char* Bp1 = (const char*)g_seqf + (((size_t)b*64*96) + ntg0 + wid*2 + 1)*256 + lane*8 + (size_t)(kh*32)*KSTR;

    unsigned (*A)[32*APITCH] = As[kh];

    float4 pa = *(const float4*)(Arow);
    pa.x *= WSCALE; pa.y *= WSCALE; pa.z *= WSCALE; pa.w *= WSCALE;
    uint2 bc0 = *(const uint2*)(Bp0);
    uint2 bc1 = *(const uint2*)(Bp1);
    stage_pairs(&A[0][arow*APITCH], quad, pa);
    __syncthreads();

    float acc[2][2][4];
    #pragma unroll
    for (int a = 0; a < 2; a++)
        #pragma unroll
        for (int n = 0; n < 2; n++)
            #pragma unroll
            for (int c = 0; c < 4; c++) acc[a][n][c] = 0.0f;

    const int NKH = 32;
    uint2 pb0, pb1;
    for (int ks = 0; ks < NKH; ks++) {
        int s = ks & 1;
        if (ks + 1 < NKH) {
            pa = *(const float4*)(Arow + (ks + 1)*16);
            pa.x *= WSCALE; pa.y *= WSCALE; pa.z *= WSCALE; pa.w *= WSCALE;
            pb0 = *(const uint2*)(Bp0 + (size_t)(ks + 1)*KSTR);
            pb1 = *(const uint2*)(Bp1 + (size_t)(ks + 1)*KSTR);
        }

        #pragma unroll
        for (int af = 0; af < 2; af++) {
            int ra = af*16 + g, rb = ra + 8;
            uint4 ua = *(const uint4*)&A[s][ra*APITCH + 4*t];
            uint4 ub = *(const uint4*)&A[s][rb*APITCH + 4*t];
            unsigned ahi[4] = {ua.x, ub.x, ua.y, ub.y};
            unsigned alo[4] = {ua.z, ub.z, ua.w, ub.w};
            mma_f16(acc[af][0], ahi, bc0.x, bc0.y);
            mma_f16(acc[af][0], alo, bc0.x, bc0.y);
            mma_f16(acc[af][1], ahi, bc1.x, bc1.y);
            mma_f16(acc[af][1], alo, bc1.x, bc1.y);
        }

        if (ks + 1 < NKH) {
            stage_pairs(&A[s^1][arow*APITCH], quad, pa);
            bc0 = pb0; bc1 = pb1;
        }
        __syncthreads();
    }

    if (kh == 1) {
        #pragma unroll
        for (int af = 0; af < 2; af++)
            #pragma unroll
            for (int nt = 0; nt < 2; nt++)
                *(float4*)&Xch[st*16 + af*8 + nt*4] =
                    make_float4(acc[af][nt][0], acc[af][nt][1], acc[af][nt][2], acc[af][nt][3]);
    }
    __syncthreads();
    if (kh == 0) {
        #pragma unroll
        for (int af = 0; af < 2; af++) {
            int ra = r0 + af*16 + g;
            #pragma unroll
            for (int nt = 0; nt < 2; nt++) {
                float4 o = *(const float4*)&Xch[st*16 + af*8 + nt*4];
                int n0 = (ntg0 + wid*2 + nt)*8 + 2*t;
                *(float2*)(g_rs + (size_t)ra*DD + n0) =
                    make_float2((acc[af][nt][0] + o.x)*WSCALE_INV, (acc[af][nt][1] + o.y)*WSCALE_INV);
                *(float2*)(g_rs + (size_t)(ra+8)*DD + n0) =
                    make_float2((acc[af][nt][2] + o.z)*WSCALE_INV, (acc[af][nt][3] + o.w)*WSCALE_INV);
            }
        }
    }
}

// ============================================================================
// K5a: Y1 = ent_emb @ W_top  (128 rows, K=768). grid (12, 4, 2), 256 thr.
// Same structure as rs kernel; A contiguous; K-split halves of 24 steps.
// ============================================================================
__global__ void __launch_bounds__(256) k_y1() {
    __shared__ __align__(16) unsigned As[2][2][32*APITCH];
    __shared__ __align__(16) float Xch[128*16];

    int ntg0 = blockIdx.x * 8;
    int r0   = blockIdx.y * 32;
    int col  = blockIdx.z;
    int tid = threadIdx.x;
    int kh  = tid >> 7;
    int st  = tid & 127;
    int wid = st >> 5, lane = st & 31;
    int g = lane >> 2, t = lane & 3;
    int arow = st >> 2, quad = st & 3;

    const float* Arow = g_ent_emb + (size_t)(r0 + arow)*DD + kh*384 + quad*4;
    const size_t KSTR = (size_t)96*256;
    const char* Bp0 = (const char*)g_Whtp + (((size_t)col*96*96) + ntg0 + wid*2    )*256 + lane*8 + (size_t)(kh*24)*KSTR;
    const char* Bp1 = (const char*)g_Whtp + (((size_t)col*96*96) + ntg0 + wid*2 + 1)*256 + lane*8 + (size_t)(kh*24)*KSTR;

    unsigned (*A)[32*APITCH] = As[kh];

    float4 pa = *(const float4*)(Arow);
    uint2 bc0 = *(const uint2*)(Bp0);
    uint2 bc1 = *(const uint2*)(Bp1);
    stage_pairs(&A[0][arow*APITCH], quad, pa);
    __syncthreads();

    float acc[2][2][4];
    #pragma unroll
    for (int a = 0; a < 2; a++)
        #pragma unroll
        for (int n = 0; n < 2; n++)
            #pragma unroll
            for (int c = 0; c < 4; c++) acc[a][n][c] = 0.0f;

    const int NKH = 24;
    uint2 pb0, pb1;
    for (int ks = 0; ks < NKH; ks++) {
        int s = ks & 1;
        if (ks + 1 < NKH) {
            pa = *(const float4*)(Arow + (ks + 1)*16);
            pb0 = *(const uint2*)(Bp0 + (size_t)(ks + 1)*KSTR);
            pb1 = *(const uint2*)(Bp1 + (size_t)(ks + 1)*KSTR);
        }

        #pragma unroll
        for (int af = 0; af < 2; af++) {
            int ra = af*16 + g, rb = ra + 8;
            uint4 ua = *(const uint4*)&A[s][ra*APITCH + 4*t];
            uint4 ub = *(const uint4*)&A[s][rb*APITCH + 4*t];
            unsigned ahi[4] = {ua.x, ub.x, ua.y, ub.y};
            unsigned alo[4] = {ua.z, ub.z, ua.w, ub.w};
            mma_f16(acc[af][0], ahi, bc0.x, bc0.y);
            mma_f16(acc[af][0], alo, bc0.x, bc0.y);
            mma_f16(acc[af][1], ahi, bc1.x, bc1.y);
            mma_f16(acc[af][1], alo, bc1.x, bc1.y);
        }

        if (ks + 1 < NKH) {
            stage_pairs(&A[s^1][arow*APITCH], quad, pa);
            bc0 = pb0; bc1 = pb1;
        }
        __syncthreads();
    }

    if (kh == 1) {
        #pragma unroll
        for (int af = 0; af < 2; af++)
            #pragma unroll
            for (int nt = 0; nt < 2; nt++)
                *(float4*)&Xch[st*16 + af*8 + nt*4] =
                    make_float4(acc[af][nt][0], acc[af][nt][1], acc[af][nt][2], acc[af][nt][3]);
    }
    __syncthreads();
    if (kh == 0) {
        float* Y = g_y1 + (size_t)col*NN*EE*DD;
        #pragma unroll
        for (int af = 0; af < 2; af++) {
            int ra = r0 + af*16 + g;
            #pragma unroll
            for (int nt = 0; nt < 2; nt++) {
                float4 o = *(const float4*)&Xch[st*16 + af*8 + nt*4];
                int n0 = (ntg0 + wid*2 + nt)*8 + 2*t;
                *(float2*)(Y + (size_t)ra*DD + n0) =
                    make_float2((acc[af][nt][0] + o.x)*WSCALE_INV, (acc[af][nt][1] + o.y)*WSCALE_INV);
                *(float2*)(Y + (size_t)(ra+8)*DD + n0) =
                    make_float2((acc[af][nt][2] + o.z)*WSCALE_INV, (acc[af][nt][3] + o.w)*WSCALE_INV);
            }
        }
    }
}

// ============================================================================
// K5b: hs2/ts2 = tanh(rs @ W_bot + Y1[ent] + bias). grid (12, 32, 2), 256 thr.
// K=768 (halves of 24 steps); A = rs rows (contiguous).
// ============================================================================
__global__ void __launch_bounds__(256) k_ht2(const float* __restrict__ bh,
                                             const float* __restrict__ bt,
                                             const int* __restrict__ hts) {
    __shared__ __align__(16) unsigned As[2][2][32*APITCH];
    __shared__ __align__(16) float Xch[128*16];
    __shared__ int eIdx[32];

    int ntg0 = blockIdx.x * 8;
    int r0   = blockIdx.y * 32;
    int col  = blockIdx.z;
    const float* bias = col ? bt : bh;
    float* outm = col ? g_ts2 : g_hs2;

    int tid = threadIdx.x;
    int kh  = tid >> 7;
    int st  = tid & 127;
    int wid = st >> 5, lane = st & 31;
    int g = lane >> 2, t = lane & 3;
    int arow = st >> 2, quad = st & 3;

    if (tid < 32) {
        int r = r0 + tid;
        eIdx[tid] = (r >> 8)*EE + hts[r*2 + col];
    }
    __syncthreads();

    const float* Arow = g_rs + (size_t)(r0 + arow)*DD + kh*384 + quad*4;
    const size_t KSTR = (size_t)96*256;
    const char* Bp0 = (const char*)g_Whtp + (((size_t)col*96*96) + ntg0 + wid*2    )*256 + lane*8 + (size_t)((48 + kh*24))*KSTR;
    const char* Bp1 = (const char*)g_Whtp + (((size_t)col*96*96) + ntg0 + wid*2 + 1)*256 + lane*8 + (size_t)((48 + kh*24))*KSTR;

    unsigned (*A)[32*APITCH] = As[kh];

    float4 pa = *(const float4*)(Arow);
    uint2 bc0 = *(const uint2*)(Bp0);
    uint2 bc1 = *(const uint2*)(Bp1);
    stage_pairs(&A[0][arow*APITCH], quad, pa);
    __syncthreads();

    float acc[2][2][4];
    #pragma unroll
    for (int a = 0; a < 2; a++)
        #pragma unroll
        for (int n = 0; n < 2; n++)
            #pragma unroll
            for (int c = 0; c < 4; c++) acc[a][n][c] = 0.0f;

    const int NKH = 24;
    uint2 pb0, pb1;
    for (int ks = 0; ks < NKH; ks++) {
        int s = ks & 1;
        if (ks + 1 < NKH) {
            pa = *(const float4*)(Arow + (ks + 1)*16);
            pb0 = *(const uint2*)(Bp0 + (size_t)(ks + 1)*KSTR);
            pb1 = *(const uint2*)(Bp1 + (size_t)(ks + 1)*KSTR);
        }

        #pragma unroll
        for (int af = 0; af < 2; af++) {
            int ra = af*16 + g, rb = ra + 8;
            uint4 ua = *(const uint4*)&A[s][ra*APITCH + 4*t];
            uint4 ub = *(const uint4*)&A[s][rb*APITCH + 4*t];
            unsigned ahi[4] = {ua.x, ub.x, ua.y, ub.y};
            unsigned alo[4] = {ua.z, ub.z, ua.w, ub.w};
            mma_f16(acc[af][0], ahi, bc0.x, bc0.y);
            mma_f16(acc[af][0], alo, bc0.x, bc0.y);
            mma_f16(acc[af][1], ahi, bc1.x, bc1.y);
            mma_f16(acc[af][1], alo, bc1.x, bc1.y);
        }

        if (ks + 1 < NKH) {
            stage_pairs(&A[s^1][arow*APITCH], quad, pa);
            bc0 = pb0; bc1 = pb1;
        }
        __syncthreads();
    }

    if (kh == 1) {
        #pragma unroll
        for (int af = 0; af < 2; af++)
            #pragma unroll
            for (int nt = 0; nt < 2; nt++)
                *(float4*)&Xch[st*16 + af*8 + nt*4] =
                    make_float4(acc[af][nt][0], acc[af][nt][1], acc[af][nt][2], acc[af][nt][3]);
    }
    __syncthreads();
    if (kh == 0) {
        const float* Y = g_y1 + (size_t)col*NN*EE*DD;
        #pragma unroll
        for (int af = 0; af < 2; af++) {
            int lrow = af*16 + g;
            int ra = r0 + lrow;
            const float* Ya = Y + (size_t)eIdx[lrow]*DD;
            const float* Yb = Y + (size_t)eIdx[lrow + 8]*DD;
            #pragma unroll
            for (int nt = 0; nt < 2; nt++) {
                float4 o = *(const float4*)&Xch[st*16 + af*8 + nt*4];
                int n0 = (ntg0 + wid*2 + nt)*8 + 2*t;
                float2 ya = *(const float2*)(Ya + n0);
                float2 yb = *(const float2*)(Yb + n0);
                float b0v = bias[n0], b1v = bias[n0 + 1];
                *(float2*)(outm + (size_t)ra*DD + n0) =
                    make_float2(tanhf((acc[af][nt][0] + o.x)*WSCALE_INV + ya.x + b0v),
                                tanhf((acc[af][nt][1] + o.y)*WSCALE_INV + ya.y + b1v));
                *(float2*)(outm + (size_t)(ra+8)*DD + n0) =
                    make_float2(tanhf((acc[af][nt][2] + o.z)*WSCALE_INV + yb.x + b0v),
                                tanhf((acc[af][nt][3] + o.w)*WSCALE_INV + yb.y + b1v));
            }
        }
    }
}

// ============================================================================
// K6: init output with bias
// ============================================================================
__global__ void k_init_out(const float* __restrict__ b_bil, float* __restrict__ out) {
    int i = blockIdx.x*256 + threadIdx.x;
    if (i < RR*NOUT) out[i] = b_bil[i % NOUT];
}

// ============================================================================
// K7: bilinear via fp16 single-term A mma (unchanged).
// ============================================================================
#define TS_OFF  0
#define HS_OFF  16896
#define WB_OFF  (HS_OFF + 64*17*4)
#define CHUNK_BYTES 3328
#define BIL_SMEM (WB_OFF + 2*CHUNK_BYTES)

__global__ void __launch_bounds__(128) k_bil_mma(float* __restrict__ out) {
    extern __shared__ __align__(16) char smem[];
    float* tsS = (float*)(smem + TS_OFF);
    float* hsS = (float*)(smem + HS_OFF);
    char*  Wbuf = smem + WB_OFF;

    const int kb = blockIdx.x >> 2;
    const int qt = blockIdx.x & 3;
    const int r0 = blockIdx.y * 64;
    const int tid  = threadIdx.x;
    const int wid  = tid >> 5;
    const int lane = tid & 31;
    const int g = lane >> 2, t = lane & 3;

    for (int idx = tid; idx < 64*64; idx += 128) {
        int rr = idx >> 6, j = idx & 63;
        tsS[rr*66 + j] = g_ts2[(size_t)(r0 + rr)*DD + kb*64 + j];
    }
    for (int idx = tid; idx < 64*16; idx += 128) {
        int rr = idx >> 4, ii = idx & 15;
        hsS[rr*17 + ii] = g_hs2[(size_t)(r0 + rr)*DD + kb*64 + qt*16 + ii];
    }
    const size_t chunk0 = (size_t)(kb*256 + qt*64);
    {
        const char* src = (const char*)g_Wp + chunk0*CHUNK_BYTES;
        for (int e = tid; e < 416; e += 128)
            *(uint2*)(Wbuf + e*8) = *(const uint2*)(src + e*8);
    }
    __syncthreads();

    float acc[13][4];
    #pragma unroll
    for (int n = 0; n < 13; n++)
        #pragma unroll
        for (int c = 0; c < 4; c++) acc[n][c] = 0.0f;

    for (int cc = 0; cc < 64; cc++) {
        int s = cc & 1;
        uint2 pw0, pw1, pw2, pw3;
        if (cc + 1 < 64) {
            const char* src = (const char*)g_Wp + (chunk0 + cc + 1)*CHUNK_BYTES;
            pw0 = *(const uint2*)(src + (tid      )*8);
            pw1 = *(const uint2*)(src + (tid + 128)*8);
            pw2 = *(const uint2*)(src + (tid + 256)*8);
            if (tid < 32) pw3 = *(const uint2*)(src + (tid + 384)*8);
        }

        int i_loc = cc >> 2;
        int j0    = (cc & 3) * 16;
        unsigned a[4];
        {
            int ra = wid*16 + g, rb = ra + 8;
            float hA = hsS[ra*17 + i_loc];
            float hB = hsS[rb*17 + i_loc];
            float2 tA0 = *(const float2*)&tsS[ra*66 + j0 + 2*t];
            float2 tA1 = *(const float2*)&tsS[ra*66 + j0 + 2*t + 8];
            float2 tB0 = *(const float2*)&tsS[rb*66 + j0 + 2*t];
            float2 tB1 = *(const float2*)&tsS[rb*66 + j0 + 2*t + 8];
            a[0] = pack_f16x2(hA*tA0.y, hA*tA0.x);
            a[1] = pack_f16x2(hB*tB0.y, hB*tB0.x);
            a[2] = pack_f16x2(hA*tA1.y, hA*tA1.x);
            a[3] = pack_f16x2(hB*tB1.y, hB*tB1.x);
        }

        #pragma unroll
        for (int nt = 0; nt < 13; nt++) {
            uint2 w = *(const uint2*)(Wbuf + s*CHUNK_BYTES + (nt*32 + lane)*8);
            mma_f16(acc[nt], a, w.x, w.y);
        }

        __syncthreads();
        if (cc + 1 < 64) {
            char* dst = Wbuf + (s^1)*CHUNK_BYTES;
            *(uint2*)(dst + (tid      )*8) = pw0;
            *(uint2*)(dst + (tid + 128)*8) = pw1;
            *(uint2*)(dst + (tid + 256)*8) = pw2;
            if (tid < 32) *(uint2*)(dst + (tid + 384)*8) = pw3;
        }
        __syncthreads();
    }

    {
        int r1 = r0 + wid*16 + g;
        #pragma unroll
        for (int nt = 0; nt < 13; nt++) {
            int n0 = nt*8 + 2*t;
            const float* av = acc[nt];
            if (n0 < NOUT) {
                atomicAdd(&out[(size_t)r1*NOUT + n0],     av[0]*WSCALE_INV);
                atomicAdd(&out[(size_t)(r1+8)*NOUT + n0], av[2]*WSCALE_INV);
            }
            if (n0 + 1 < NOUT) {
                atomicAdd(&out[(size_t)r1*NOUT + n0 + 1],     av[1]*WSCALE_INV);
                atomicAdd(&out[(size_t)(r1+8)*NOUT + n0 + 1], av[3]*WSCALE_INV);
            }
        }
    }
}

// ============================================================================
// launch: multi-stream DAG; k_rs_mma kept 4th for profiling.
// ============================================================================
extern "C" void kernel_launch(void* const* d_in, const int* in_sizes, int n_in,
                              void* d_out, int out_size) {
    const float* seq    = (const float*)d_in[0];
    const float* att    = (const float*)d_in[1];
    const int*   mpos   = (const int*  )d_in[2];
    const int*   hts    = (const int*  )d_in[3];
    const float* W_head = (const float*)d_in[4];
    const float* b_head = (const float*)d_in[5];
    const float* W_tail = (const float*)d_in[6];
    const float* b_tail = (const float*)d_in[7];
    const float* W_bil  = (const float*)d_in[8];
    const float* b_bil  = (const float*)d_in[9];
    float* out = (float*)d_out;

    static cudaStream_t s1, s2, s3;
    static cudaEvent_t evRoot, evA, evB, evC, evD, evF, evY;
    static int inited = 0;
    if (!inited) {
        cudaStreamCreateWithFlags(&s1, cudaStreamNonBlocking);
        cudaStreamCreateWithFlags(&s2, cudaStreamNonBlocking);
        cudaStreamCreateWithFlags(&s3, cudaStreamNonBlocking);
        cudaEventCreateWithFlags(&evRoot, cudaEventDisableTiming);
        cudaEventCreateWithFlags(&evA, cudaEventDisableTiming);
        cudaEventCreateWithFlags(&evB, cudaEventDisableTiming);
        cudaEventCreateWithFlags(&evC, cudaEventDisableTiming);
        cudaEventCreateWithFlags(&evD, cudaEventDisableTiming);
        cudaEventCreateWithFlags(&evF, cudaEventDisableTiming);
        cudaEventCreateWithFlags(&evY, cudaEventDisableTiming);
        cudaFuncSetAttribute(k_bil_mma, cudaFuncAttributeMaxDynamicSharedMemorySize, BIL_SMEM);
        inited = 1;
    }

    cudaEventRecord(evRoot, 0);
    cudaStreamWaitEvent(s1, evRoot, 0);
    cudaStreamWaitEvent(s2, evRoot, 0);
    cudaStreamWaitEvent(s3, evRoot, 0);

    k_ent_att<<<NN*EE*HH, 256>>>(att, mpos);                    // 1 (main)
    k_ht_att<<<NN*PP, 256>>>(hts);                              // 2 (main)
    k_seqf<<<dim3(64, 4), 256, 0, s2>>>(seq);                   // 3 (s2)
    cudaEventRecord(evC, s2);
    cudaStreamWaitEvent(0, evC, 0);
    k_rs_mma<<<dim3(12, 32), 256>>>();                          // 4 (main) <- profiled
    k_wht<<<dim3(96, 2), 256, 0, s2>>>(W_head, W_tail);         // 5 (s2)
    cudaEventRecord(evB, s2);
    k_ent_emb<<<dim3(NN*EE, 2), 256, 0, s3>>>(seq, mpos);       // 6 (s3)
    // y1 on s3: needs ent_emb (same stream) + wht (evB)
    cudaStreamWaitEvent(s3, evB, 0);
    k_y1<<<dim3(12, 4, 2), 256, 0, s3>>>();                     // 7 (s3)
    cudaEventRecord(evY, s3);
    cudaStreamWaitEvent(0, evB, 0);
    cudaStreamWaitEvent(0, evY, 0);
    k_ht2<<<dim3(12, 32, 2), 256>>>(b_head, b_tail, hts);       // 8 (main)
    k_wt<<<3072, 128, 0, s1>>>(W_bil);                          // 9 (s1)
    cudaEventRecord(evA, s1);
    k_init_out<<<(RR*NOUT + 255)/256, 256, 0, s3>>>(b_bil, out);// 10 (s3)
    cudaEventRecord(evF, s3);
    cudaStreamWaitEvent(0, evA, 0);
    cudaStreamWaitEvent(0, evF, 0);
    k_bil_mma<<<dim3(KBL*4, RR/64), 128, BIL_SMEM>>>(out);      // 11 (main)
}

// round 16
// speedup vs baseline: 1.1946x; 1.0250x over previous
#include <cuda_runtime.h>
#include <math.h>

// ---------------- fixed problem shapes ----------------
#define NN   4
#define CC   1024
#define DD   768
#define HH   12
#define EE   32
#define MM   4
#define PP   256
#define RR   (NN*PP)     // 1024
#define KBL  12
#define NOUT 97

#define WSCALE     1024.0f
#define WSCALE_INV (1.0f/1024.0f)

// ---------------- scratch ----------------
__device__ float g_ent_emb[NN*EE*DD];
__device__ float g_ent_att[NN*EE*HH*CC];
__device__ float g_rs     [RR*DD];        // kept for y1-path compatibility (unused now)
__device__ float g_hs2    [RR*DD];
__device__ float g_ts2    [RR*DD];
__device__ float g_y1     [2*NN*EE*DD];

// fragment-packed A operands (split fp16, pair_slot layout, 16 u32 / row / kstep)
__device__ __align__(16) unsigned g_htaf[RR*64*16];   // ht_att x1024, 4 MB
__device__ __align__(16) unsigned g_rsf [RR*48*16];   // rs (unscaled), 3 MB

// W_bil fragments (fp16, x1024)
__device__ __align__(16) unsigned char g_Wp[3072UL*13*32*8];
// W_head/W_tail fragments (fp16, x1024): [2][96 kc][96 nt][32] uint2
__device__ __align__(16) unsigned char g_Whtp[2UL*96*96*32*8];
// seq fragments (fp16, unscaled): [4][64 kc][96 nt][32] uint2
__device__ __align__(16) unsigned char g_seqf[4UL*64*96*32*8];

// ---------------- fp16 helpers ----------------
__device__ __forceinline__ unsigned pack_f16x2(float hi_f, float lo_f) {
    unsigned r;
    asm("cvt.rn.f16x2.f32 %0, %1, %2;" : "=r"(r) : "f"(hi_f), "f"(lo_f));
    return r;
}
__device__ __forceinline__ void split2h(float p0, float p1, unsigned& hi, unsigned& lo) {
    hi = pack_f16x2(p1, p0);
    float f0, f1;
    asm("{\n\t.reg .b16 h0, h1;\n\t"
        "mov.b32 {h0, h1}, %2;\n\t"
        "cvt.f32.f16 %0, h0;\n\t"
        "cvt.f32.f16 %1, h1;\n\t}"
        : "=f"(f0), "=f"(f1) : "r"(hi));
    lo = pack_f16x2(p1 - f1, p0 - f0);
}
__device__ __forceinline__ void mma_f16(float* d, const unsigned* a,
                                        unsigned b0, unsigned b1) {
    asm volatile(
        "mma.sync.aligned.m16n8k16.row.col.f32.f16.f16.f32 "
        "{%0,%1,%2,%3}, {%4,%5,%6,%7}, {%8,%9}, {%0,%1,%2,%3};"
        : "+f"(d[0]), "+f"(d[1]), "+f"(d[2]), "+f"(d[3])
        : "r"(a[0]), "r"(a[1]), "r"(a[2]), "r"(a[3]), "r"(b0), "r"(b1));
}
__device__ __forceinline__ int pair_slot(int p) {
    return (p < 4) ? 4*p : 4*(p - 4) + 1;
}
// stage one float4 into packed fragment row (for y1 smem staging)
__device__ __forceinline__ void stage_pairs(unsigned* dst_row, int quad, float4 v) {
    unsigned hi0, lo0, hi1, lo1;
    split2h(v.x, v.y, hi0, lo0);
    split2h(v.z, v.w, hi1, lo1);
    int p0 = quad*2, p1 = p0 + 1;
    int s0 = pair_slot(p0), s1 = pair_slot(p1);
    dst_row[s0] = hi0; dst_row[s0 + 2] = lo0;
    dst_row[s1] = hi1; dst_row[s1 + 2] = lo1;
}

// ============================================================================
// P0: pack W_bil. grid 3072, 128 thr
// ============================================================================
__global__ void k_wt(const float* __restrict__ Wb) {
    __shared__ float Wsm[16*104];
    int chunk = blockIdx.x;
    int tid = threadIdx.x;
    int row0 = chunk * 16;

    for (int idx = tid; idx < 16*104; idx += 128) {
        int r = idx / 104, n = idx - r*104;
        Wsm[idx] = (n < NOUT) ? Wb[(size_t)(row0 + r)*NOUT + n] * WSCALE : 0.0f;
    }
    __syncthreads();

    for (int e = tid; e < 13*32; e += 128) {
        int nt = e >> 5, lane = e & 31;
        int g = lane >> 2, t = lane & 3;
        int n = nt*8 + g, k0 = 2*t;
        unsigned b0 = pack_f16x2(Wsm[(k0 + 1)*104 + n], Wsm[(k0    )*104 + n]);
        unsigned b1 = pack_f16x2(Wsm[(k0 + 9)*104 + n], Wsm[(k0 + 8)*104 + n]);
        *(uint2*)(g_Wp + ((size_t)(chunk*13 + nt)*32 + lane)*8) = make_uint2(b0, b1);
    }
}

// ============================================================================
// P1: pack W_head / W_tail. grid (96, 2), 256 thr
// ============================================================================
__global__ void k_wht(const float* __restrict__ Wh, const float* __restrict__ Wt) {
    __shared__ float S[16*768];
    int kc = blockIdx.x;
    int w  = blockIdx.y;
    const float* W = w ? Wt : Wh;
    int tid = threadIdx.x;

    for (int idx = tid; idx < 16*768; idx += 256)
        S[idx] = W[(size_t)kc*16*768 + idx] * WSCALE;
    __syncthreads();

    for (int e = tid; e < 96*32; e += 256) {
        int nt = e >> 5, lane = e & 31;
        int g = lane >> 2, t = lane & 3;
        int n = nt*8 + g, k0 = 2*t;
        unsigned b0 = pack_f16x2(S[(k0 + 1)*768 + n], S[(k0    )*768 + n]);
        unsigned b1 = pack_f16x2(S[(k0 + 9)*768 + n], S[(k0 + 8)*768 + n]);
        *(uint2*)(g_Whtp + ((((size_t)w*96 + kc)*96 + nt)*32 + lane)*8) = make_uint2(b0, b1);
    }
}

// ============================================================================
// P2: pack seq. grid (64, 4), 256 thr
// ============================================================================
__global__ void k_seqf(const float* __restrict__ seq) {
    __shared__ float S[16*768];
    int kc = blockIdx.x;
    int b  = blockIdx.y;
    int tid = threadIdx.x;

    for (int idx = tid; idx < 16*768; idx += 256)
        S[idx] = seq[((size_t)b*CC + kc*16)*768 + idx];
    __syncthreads();

    for (int e = tid; e < 96*32; e += 256) {
        int nt = e >> 5, lane = e & 31;
        int g = lane >> 2, t = lane & 3;
        int n = nt*8 + g, k0 = 2*t;
        unsigned b0 = pack_f16x2(S[(k0 + 1)*768 + n], S[(k0    )*768 + n]);
        unsigned b1 = pack_f16x2(S[(k0 + 9)*768 + n], S[(k0 + 8)*768 + n]);
        *(uint2*)(g_seqf + ((((size_t)b*64 + kc)*96 + nt)*32 + lane)*8) = make_uint2(b0, b1);
    }
}

// ============================================================================
// K1: entity embeddings = logsumexp. grid (128, 2)
// ============================================================================
__global__ void k_ent_emb(const float* __restrict__ seq,
                          const int*   __restrict__ mpos) {
    int be = blockIdx.x;
    int half = blockIdx.y;
    int b  = be / EE;
    const int* mp = mpos + be*MM;
    int p0 = mp[0], p1 = mp[1], p2 = mp[2], p3 = mp[3];
    const float* sb = seq + (long)b*CC*DD;
    int d0 = half*(DD/2), d1 = d0 + DD/2;
    for (int dd = d0 + threadIdx.x; dd < d1; dd += blockDim.x) {
        float v0 = sb[p0*DD+dd], v1 = sb[p1*DD+dd];
        float v2 = sb[p2*DD+dd], v3 = sb[p3*DD+dd];
        float mx = fmaxf(fmaxf(v0, v1), fmaxf(v2, v3));
        float s  = expf(v0-mx) + expf(v1-mx) + expf(v2-mx) + expf(v3-mx);
        g_ent_emb[be*DD + dd] = mx + logf(s);
    }
}

// ============================================================================
// K2: entity attention = mean over mention attention rows
// ============================================================================
__global__ void k_ent_att(const float* __restrict__ att,
                          const int*   __restrict__ mpos) {
    int id = blockIdx.x;
    int hd = id % HH;
    int be = id / HH;
    int b  = be / EE;
    const int* mp = mpos + be*MM;
    const float* ab = att + (long)(b*HH + hd)*CC*CC;
    float* ob = g_ent_att + (long)id*CC;
    int q0 = mp[0]*CC, q1 = mp[1]*CC, q2 = mp[2]*CC, q3 = mp[3]*CC;
    for (int c = threadIdx.x; c < CC; c += blockDim.x) {
        float s = ab[q0+c] + ab[q1+c] + ab[q2+c] + ab[q3+c];
        ob[c] = s * 0.25f;
    }
}

// ============================================================================
// K3: ht_att = mean_h(h_att*t_att), normalized, emitted as A-FRAGMENTS
// (x1024, split fp16, pair_slot layout). grid RR, 256 thr.
// Thread handles pairs (2tid, 2tid+1) and (2tid+512, 2tid+513).
// ============================================================================
__global__ void k_ht_att(const int* __restrict__ hts) {
    int bp = blockIdx.x;
    int b  = bp / PP;
    int eh = hts[bp*2 + 0];
    int et = hts[bp*2 + 1];
    const float* ah = g_ent_att + (long)(b*EE + eh)*HH*CC;
    const float* at = g_ent_att + (long)(b*EE + et)*HH*CC;
    int tid = threadIdx.x;

    float v[4];
    float lsum = 0.f;
    #pragma unroll
    for (int q = 0; q < 2; q++) {
        int c0 = q*512 + 2*tid;
        #pragma unroll
        for (int j = 0; j < 2; j++) {
            int c = c0 + j;
            float s = 0.f;
            #pragma unroll
            for (int hd = 0; hd < HH; hd++)
                s += ah[hd*CC + c] * at[hd*CC + c];
            v[q*2 + j] = s * (1.0f / HH);
            lsum += s * (1.0f / HH);
        }
    }
    __shared__ float red[256];
    red[tid] = lsum;
    __syncthreads();
    for (int st = 128; st > 0; st >>= 1) {
        if (tid < st) red[tid] += red[tid + st];
        __syncthreads();
    }
    float scl = WSCALE / (red[0] + 1e-30f);

    unsigned* base = g_htaf + (size_t)bp*64*16;
    #pragma unroll
    for (int q = 0; q < 2; q++) {
        int p  = q*256 + tid;            // pair index 0..511
        int ks = p >> 3, pl = p & 7;
        int slot = pair_slot(pl);
        unsigned hi, lo;
        split2h(v[q*2]*scl, v[q*2 + 1]*scl, hi, lo);
        base[ks*16 + slot]     = hi;
        base[ks*16 + slot + 2] = lo;
    }
}

// ============================================================================
// K4: rs = ht_att @ seq. A from g_htaf fragments (global), NO smem staging,
// NO main-loop barriers. grid (12, 32), 256 thr, K-split x2.
// Epilogue writes g_rsf fragments (unscaled) for ht2.
// ============================================================================
__global__ void __launch_bounds__(256) k_rs_mma() {
    __shared__ __align__(16) float Xch[128*16];

    int ntg0 = blockIdx.x * 8;
    int r0   = blockIdx.y * 32;
    int b    = r0 >> 8;
    int tid = threadIdx.x;
    int kh  = tid >> 7;
    int st  = tid & 127;
    int wid = st >> 5, lane = st & 31;
    int g = lane >> 2, t = lane & 3;

    const unsigned* Af0 = g_htaf + ((size_t)(r0 + g     )*64 + kh*32)*16 + 4*t;
    const unsigned* Af1 = Af0 + (size_t) 8*64*16;
    const unsigned* Af2 = Af0 + (size_t)16*64*16;
    const unsigned* Af3 = Af0 + (size_t)24*64*16;

    const size_t KSTR = (size_t)96*256;
    const char* Bp0 = (const char*)g_seqf + (((size_t)b*64*96) + ntg0 + wid*2    )*256 + lane*8 + (size_t)(kh*32)*KSTR;
    const char* Bp1 = (const char*)g_seqf + (((size_t)b*64*96) + ntg0 + wid*2 + 1)*256 + lane*8 + (size_t)(kh*32)*KSTR;

    float acc[2][2][4];
    #pragma unroll
    for (int a = 0; a < 2; a++)
        #pragma unroll
        for (int n = 0; n < 2; n++)
            #pragma unroll
            for (int c = 0; c < 4; c++) acc[a][n][c] = 0.0f;

    // depth-1 register prefetch
    uint4 ua = *(const uint4*)(Af0), ub = *(const uint4*)(Af1);
    uint4 uc = *(const uint4*)(Af2), ud = *(const uint4*)(Af3);
    uint2 bc0 = *(const uint2*)(Bp0), bc1 = *(const uint2*)(Bp1);

    const int NKH = 32;
    for (int ks = 0; ks < NKH; ks++) {
        uint4 na, nb, nc, nd; uint2 n0, n1;
        if (ks + 1 < NKH) {
            na = *(const uint4*)(Af0 + (ks + 1)*16);
            nb = *(const uint4*)(Af1 + (ks + 1)*16);
            nc = *(const uint4*)(Af2 + (ks + 1)*16);
            nd = *(const uint4*)(Af3 + (ks + 1)*16);
            n0 = *(const uint2*)(Bp0 + (size_t)(ks + 1)*KSTR);
            n1 = *(const uint2*)(Bp1 + (size_t)(ks + 1)*KSTR);
        }
        {
            unsigned ahi0[4] = {ua.x, ub.x, ua.y, ub.y};
            unsigned alo0[4] = {ua.z, ub.z, ua.w, ub.w};
            unsigned ahi1[4] = {uc.x, ud.x, uc.y, ud.y};
            unsigned alo1[4] = {uc.z, ud.z, uc.w, ud.w};
            mma_f16(acc[0][0], ahi0, bc0.x, bc0.y);
            mma_f16(acc[0][0], alo0, bc0.x, bc0.y);
            mma_f16(acc[0][1], ahi0, bc1.x, bc1.y);
            mma_f16(acc[0][1], alo0, bc1.x, bc1.y);
            mma_f16(acc[1][0], ahi1, bc0.x, bc0.y);
            mma_f16(acc[1][0], alo1, bc0.x, bc0.y);
            mma_f16(acc[1][1], ahi1, bc1.x, bc1.y);
            mma_f16(acc[1][1], alo1, bc1.x, bc1.y);
        }
        ua = na; ub = nb; uc = nc; ud = nd; bc0 = n0; bc1 = n1;
    }

    if (kh == 1) {
        #pragma unroll
        for (int af = 0; af < 2; af++)
            #pragma unroll
            for (int nt = 0; nt < 2; nt++)
                *(float4*)&Xch[st*16 + af*8 + nt*4] =
                    make_float4(acc[af][nt][0], acc[af][nt][1], acc[af][nt][2], acc[af][nt][3]);
    }
    __syncthreads();
    if (kh == 0) {
        #pragma unroll
        for (int af = 0; af < 2; af++) {
            int ra = r0 + af*16 + g;
            #pragma unroll
            for (int nt = 0; nt < 2; nt++) {
                float4 o = *(const float4*)&Xch[st*16 + af*8 + nt*4];
                int p  = (ntg0 + wid*2 + nt)*4 + t;     // pair index in ht2's K
                int ks = p >> 3, slot = pair_slot(p & 7);
                float va0 = (acc[af][nt][0] + o.x)*WSCALE_INV;
                float va1 = (acc[af][nt][1] + o.y)*WSCALE_INV;
                float vb0 = (acc[af][nt][2] + o.z)*WSCALE_INV;
                float vb1 = (acc[af][nt][3] + o.w)*WSCALE_INV;
                unsigned hi, lo;
                split2h(va0, va1, hi, lo);
                unsigned* da = g_rsf + ((size_t)ra*48 + ks)*16;
                da[slot] = hi; da[slot + 2] = lo;
                split2h(vb0, vb1, hi, lo);
                unsigned* db = g_rsf + ((size_t)(ra + 8)*48 + ks)*16;
                db[slot] = hi; db[slot + 2] = lo;
            }
        }
    }
}

// ============================================================================
// K5a: Y1 = ent_emb @ W_top (128 rows, K=768). grid (12, 4, 2), 256 thr.
// (smem-staged variant; small, off critical path)
// ============================================================================
#define APITCH 20
__global__ void __launch_bounds__(256) k_y1() {
    __shared__ __align__(16) unsigned As[2][2][32*APITCH];
    __shared__ __align__(16) float Xch[128*16];

    int ntg0 = blockIdx.x * 8;
    int r0   = blockIdx.y * 32;
    int col  = blockIdx.z;
    int tid = threadIdx.x;
    int kh  = tid >> 7;
    int st  = tid & 127;
    int wid = st >> 5, lane = st & 31;
    int g = lane >> 2, t = lane & 3;
    int arow = st >> 2, quad = st & 3;

    const float* Arow = g_ent_emb + (size_t)(r0 + arow)*DD + kh*384 + quad*4;
    const size_t KSTR = (size_t)96*256;
    const char* Bp0 = (const char*)g_Whtp + (((size_t)col*96*96) + ntg0 + wid*2    )*256 + lane*8 + (size_t)(kh*24)*KSTR;
    const char* Bp1 = (const char*)g_Whtp + (((size_t)col*96*96) + ntg0 + wid*2 + 1)*256 + lane*8 + (size_t)(kh*24)*KSTR;

    unsigned (*A)[32*APITCH] = As[kh];

    float4 pa = *(const float4*)(Arow);
    uint2 bc0 = *(const uint2*)(Bp0);
    uint2 bc1 = *(const uint2*)(Bp1);
    stage_pairs(&A[0][arow*APITCH], quad, pa);
    __syncthreads();

    float acc[2][2][4];
    #pragma unroll
    for (int a = 0; a < 2; a++)
        #pragma unroll
        for (int n = 0; n < 2; n++)
            #pragma unroll
            for (int c = 0; c < 4; c++) acc[a][n][c] = 0.0f;

    const int NKH = 24;
    uint2 pb0, pb1;
    for (int ks = 0; ks < NKH; ks++) {
        int s = ks & 1;
        if (ks + 1 < NKH) {
            pa = *(const float4*)(Arow + (ks + 1)*16);
            pb0 = *(const uint2*)(Bp0 + (size_t)(ks + 1)*KSTR);
            pb1 = *(const uint2*)(Bp1 + (size_t)(ks + 1)*KSTR);
        }
        #pragma unroll
        for (int af = 0; af < 2; af++) {
            int ra = af*16 + g, rb = ra + 8;
            uint4 ua = *(const uint4*)&A[s][ra*APITCH + 4*t];
            uint4 ub = *(const uint4*)&A[s][rb*APITCH + 4*t];
            unsigned ahi[4] = {ua.x, ub.x, ua.y, ub.y};
            unsigned alo[4] = {ua.z, ub.z, ua.w, ub.w};
            mma_f16(acc[af][0], ahi, bc0.x, bc0.y);
            mma_f16(acc[af][0], alo, bc0.x, bc0.y);
            mma_f16(acc[af][1], ahi, bc1.x, bc1.y);
            mma_f16(acc[af][1], alo, bc1.x, bc1.y);
        }
        if (ks + 1 < NKH) {
            stage_pairs(&A[s^1][arow*APITCH], quad, pa);
            bc0 = pb0; bc1 = pb1;
        }
        __syncthreads();
    }

    if (kh == 1) {
        #pragma unroll
        for (int af = 0; af < 2; af++)
            #pragma unroll
            for (int nt = 0; nt < 2; nt++)
                *(float4*)&Xch[st*16 + af*8 + nt*4] =
                    make_float4(acc[af][nt][0], acc[af][nt][1], acc[af][nt][2], acc[af][nt][3]);
    }
    __syncthreads();
    if (kh == 0) {
        float* Y = g_y1 + (size_t)col*NN*EE*DD;
        #pragma unroll
        for (int af = 0; af < 2; af++) {
            int ra = r0 + af*16 + g;
            #pragma unroll
            for (int nt = 0; nt < 2; nt++) {
                float4 o = *(const float4*)&Xch[st*16 + af*8 + nt*4];
                int n0 = (ntg0 + wid*2 + nt)*8 + 2*t;
                *(float2*)(Y + (size_t)ra*DD + n0) =
                    make_float2((acc[af][nt][0] + o.x)*WSCALE_INV, (acc[af][nt][1] + o.y)*WSCALE_INV);
                *(float2*)(Y + (size_t)(ra+8)*DD + n0) =
                    make_float2((acc[af][nt][2] + o.z)*WSCALE_INV, (acc[af][nt][3] + o.w)*WSCALE_INV);
            }
        }
    }
}

// ============================================================================
// K5b: hs2/ts2 = tanh(rs @ W_bot + Y1[ent] + bias). A from g_rsf fragments,
// NO smem staging, NO main-loop barriers. grid (12, 32, 2), 256 thr.
// ============================================================================
__global__ void __launch_bounds__(256) k_ht2(const float* __restrict__ bh,
                                             const float* __restrict__ bt,
                                             const int* __restrict__ hts) {
    __shared__ __align__(16) float Xch[128*16];
    __shared__ int eIdx[32];

    int ntg0 = blockIdx.x * 8;
    int r0   = blockIdx.y * 32;
    int col  = blockIdx.z;
    const float* bias = col ? bt : bh;
    float* outm = col ? g_ts2 : g_hs2;

    int tid = threadIdx.x;
    int kh  = tid >> 7;
    int st  = tid & 127;
    int wid = st >> 5, lane = st & 31;
    int g = lane >> 2, t = lane & 3;

    if (tid < 32) {
        int r = r0 + tid;
        eIdx[tid] = (r >> 8)*EE + hts[r*2 + col];
    }

    const unsigned* Af0 = g_rsf + ((size_t)(r0 + g     )*48 + kh*24)*16 + 4*t;
    const unsigned* Af1 = Af0 + (size_t) 8*48*16;
    const unsigned* Af2 = Af0 + (size_t)16*48*16;
    const unsigned* Af3 = Af0 + (size_t)24*48*16;

    const size_t KSTR = (size_t)96*256;
    const char* Bp0 = (const char*)g_Whtp + (((size_t)col*96*96) + ntg0 + wid*2    )*256 + lane*8 + (size_t)(48 + kh*24)*KSTR;
    const char* Bp1 = (const char*)g_Whtp + (((size_t)col*96*96) + ntg0 + wid*2 + 1)*256 + lane*8 + (size_t)(48 + kh*24)*KSTR;

    float acc[2][2][4];
    #pragma unroll
    for (int a = 0; a < 2; a++)
        #pragma unroll
        for (int n = 0; n < 2; n++)
            #pragma unroll
            for (int c = 0; c < 4; c++) acc[a][n][c] = 0.0f;

    uint4 ua = *(const uint4*)(Af0), ub = *(const uint4*)(Af1);
    uint4 uc = *(const uint4*)(Af2), ud = *(const uint4*)(Af3);
    uint2 bc0 = *(const uint2*)(Bp0), bc1 = *(const uint2*)(Bp1);

    const int NKH = 24;
    for (int ks = 0; ks < NKH; ks++) {
        uint4 na, nb, nc, nd; uint2 n0, n1;
        if (ks + 1 < NKH) {
            na = *(const uint4*)(Af0 + (ks + 1)*16);
            nb = *(const uint4*)(Af1 + (ks + 1)*16);
            nc = *(const uint4*)(Af2 + (ks + 1)*16);
            nd = *(const uint4*)(Af3 + (ks + 1)*16);
            n0 = *(const uint2*)(Bp0 + (size_t)(ks + 1)*KSTR);
            n1 = *(const uint2*)(Bp1 + (size_t)(ks + 1)*KSTR);
        }
        {
            unsigned ahi0[4] = {ua.x, ub.x, ua.y, ub.y};
            unsigned alo0[4] = {ua.z, ub.z, ua.w, ub.w};
            unsigned ahi1[4] = {uc.x, ud.x, uc.y, ud.y};
            unsigned alo1[4] = {uc.z, ud.z, uc.w, ud.w};
            mma_f16(acc[0][0], ahi0, bc0.x, bc0.y);
            mma_f16(acc[0][0], alo0, bc0.x, bc0.y);
            mma_f16(acc[0][1], ahi0, bc1.x, bc1.y);
            mma_f16(acc[0][1], alo0, bc1.x, bc1.y);
            mma_f16(acc[1][0], ahi1, bc0.x, bc0.y);
            mma_f16(acc[1][0], alo1, bc0.x, bc0.y);
            mma_f16(acc[1][1], ahi1, bc1.x, bc1.y);
            mma_f16(acc[1][1], alo1, bc1.x, bc1.y);
        }
        ua = na; ub = nb; uc = nc; ud = nd; bc0 = n0; bc1 = n1;
    }

    if (kh == 1) {
        #pragma unroll
        for (int af = 0; af < 2; af++)
            #pragma unroll
            for (int nt = 0; nt < 2; nt++)
                *(float4*)&Xch[st*16 + af*8 + nt*4] =
                    make_float4(acc[af][nt][0], acc[af][nt][1], acc[af][nt][2], acc[af][nt][3]);
    }
    __syncthreads();
    if (kh == 0) {
        const float* Y = g_y1 + (size_t)col*NN*EE*DD;
        #pragma unroll
        for (int af = 0; af < 2; af++) {
            int lrow = af*16 + g;
            int ra = r0 + lrow;
            const float* Ya = Y + (size_t)eIdx[lrow]*DD;
            const float* Yb = Y + (size_t)eIdx[lrow + 8]*DD;
            #pragma unroll
            for (int nt = 0; nt < 2; nt++) {
                float4 o = *(const float4*)&Xch[st*16 + af*8 + nt*4];
                int n0 = (ntg0 + wid*2 + nt)*8 + 2*t;
                float2 ya = *(const float2*)(Ya + n0);
                float2 yb = *(const float2*)(Yb + n0);
                float b0v = bias[n0], b1v = bias[n0 + 1];
                *(float2*)(outm + (size_t)ra*DD + n0) =
                    make_float2(tanhf((acc[af][nt][0] + o.x)*WSCALE_INV + ya.x + b0v),
                                tanhf((acc[af][nt][1] + o.y)*WSCALE_INV + ya.y + b1v));
                *(float2*)(outm + (size_t)(ra+8)*DD + n0) =
                    make_float2(tanhf((acc[af][nt][2] + o.z)*WSCALE_INV + yb.x + b0v),
                                tanhf((acc[af][nt][3] + o.w)*WSCALE_INV + yb.y + b1v));
            }
        }
    }
}

// ============================================================================
// K6: init output with bias
// ============================================================================
__global__ void k_init_out(const float* __restrict__ b_bil, float* __restrict__ out) {
    int i = blockIdx.x*256 + threadIdx.x;
    if (i < RR*NOUT) out[i] = b_bil[i % NOUT];
}

// ============================================================================
// K7: bilinear via fp16 single-term A mma (unchanged).
// ============================================================================
#define TS_OFF  0
#define HS_OFF  16896
#define WB_OFF  (HS_OFF + 64*17*4)
#define CHUNK_BYTES 3328
#define BIL_SMEM (WB_OFF + 2*CHUNK_BYTES)

__global__ void __launch_bounds__(128) k_bil_mma(float* __restrict__ out) {
    extern __shared__ __align__(16) char smem[];
    float* tsS = (float*)(smem + TS_OFF);
    float* hsS = (float*)(smem + HS_OFF);
    char*  Wbuf = smem + WB_OFF;

    const int kb = blockIdx.x >> 2;
    const int qt = blockIdx.x & 3;
    const int r0 = blockIdx.y * 64;
    const int tid  = threadIdx.x;
    const int wid  = tid >> 5;
    const int lane = tid & 31;
    const int g = lane >> 2, t = lane & 3;

    for (int idx = tid; idx < 64*64; idx += 128) {
        int rr = idx >> 6, j = idx & 63;
        tsS[rr*66 + j] = g_ts2[(size_t)(r0 + rr)*DD + kb*64 + j];
    }
    for (int idx = tid; idx < 64*16; idx += 128) {
        int rr = idx >> 4, ii = idx & 15;
        hsS[rr*17 + ii] = g_hs2[(size_t)(r0 + rr)*DD + kb*64 + qt*16 + ii];
    }
    const size_t chunk0 = (size_t)(kb*256 + qt*64);
    {
        const char* src = (const char*)g_Wp + chunk0*CHUNK_BYTES;
        for (int e = tid; e < 416; e += 128)
            *(uint2*)(Wbuf + e*8) = *(const uint2*)(src + e*8);
    }
    __syncthreads();

    float acc[13][4];
    #pragma unroll
    for (int n = 0; n < 13; n++)
        #pragma unroll
        for (int c = 0; c < 4; c++) acc[n][c] = 0.0f;

    for (int cc = 0; cc < 64; cc++) {
        int s = cc & 1;
        uint2 pw0, pw1, pw2, pw3;
        if (cc + 1 < 64) {
            const char* src = (const char*)g_Wp + (chunk0 + cc + 1)*CHUNK_BYTES;
            pw0 = *(const uint2*)(src + (tid      )*8);
            pw1 = *(const uint2*)(src + (tid + 128)*8);
            pw2 = *(const uint2*)(src + (tid + 256)*8);
            if (tid < 32) pw3 = *(const uint2*)(src + (tid + 384)*8);
        }

        int i_loc = cc >> 2;
        int j0    = (cc & 3) * 16;
        unsigned a[4];
        {
            int ra = wid*16 + g, rb = ra + 8;
            float hA = hsS[ra*17 + i_loc];
            float hB = hsS[rb*17 + i_loc];
            float2 tA0 = *(const float2*)&tsS[ra*66 + j0 + 2*t];
            float2 tA1 = *(const float2*)&tsS[ra*66 + j0 + 2*t + 8];
            float2 tB0 = *(const float2*)&tsS[rb*66 + j0 + 2*t];
            float2 tB1 = *(const float2*)&tsS[rb*66 + j0 + 2*t + 8];
            a[0] = pack_f16x2(hA*tA0.y, hA*tA0.x);
            a[1] = pack_f16x2(hB*tB0.y, hB*tB0.x);
            a[2] = pack_f16x2(hA*tA1.y, hA*tA1.x);
            a[3] = pack_f16x2(hB*tB1.y, hB*tB1.x);
        }

        #pragma unroll
        for (int nt = 0; nt < 13; nt++) {
            uint2 w = *(const uint2*)(Wbuf + s*CHUNK_BYTES + (nt*32 + lane)*8);
            mma_f16(acc[nt], a, w.x, w.y);
        }

        __syncthreads();
        if (cc + 1 < 64) {
            char* dst = Wbuf + (s^1)*CHUNK_BYTES;
            *(uint2*)(dst + (tid      )*8) = pw0;
            *(uint2*)(dst + (tid + 128)*8) = pw1;
            *(uint2*)(dst + (tid + 256)*8) = pw2;
            if (tid < 32) *(uint2*)(dst + (tid + 384)*8) = pw3;
        }
        __syncthreads();
    }

    {
        int r1 = r0 + wid*16 + g;
        #pragma unroll
        for (int nt = 0; nt < 13; nt++) {
            int n0 = nt*8 + 2*t;
            const float* av = acc[nt];
            if (n0 < NOUT) {
                atomicAdd(&out[(size_t)r1*NOUT + n0],     av[0]*WSCALE_INV);
                atomicAdd(&out[(size_t)(r1+8)*NOUT + n0], av[2]*WSCALE_INV);
            }
            if (n0 + 1 < NOUT) {
                atomicAdd(&out[(size_t)r1*NOUT + n0 + 1],     av[1]*WSCALE_INV);
                atomicAdd(&out[(size_t)(r1+8)*NOUT + n0 + 1], av[3]*WSCALE_INV);
            }
        }
    }
}

// ============================================================================
// launch: multi-stream DAG; k_rs_mma kept 4th for profiling.
// ============================================================================
extern "C" void kernel_launch(void* const* d_in, const int* in_sizes, int n_in,
                              void* d_out, int out_size) {
    const float* seq    = (const float*)d_in[0];
    const float* att    = (const float*)d_in[1];
    const int*   mpos   = (const int*  )d_in[2];
    const int*   hts    = (const int*  )d_in[3];
    const float* W_head = (const float*)d_in[4];
    const float* b_head = (const float*)d_in[5];
    const float* W_tail = (const float*)d_in[6];
    const float* b_tail = (const float*)d_in[7];
    const float* W_bil  = (const float*)d_in[8];
    const float* b_bil  = (const float*)d_in[9];
    float* out = (float*)d_out;

    static cudaStream_t s1, s2, s3;
    static cudaEvent_t evRoot, evA, evB, evC, evF, evY;
    static int inited = 0;
    if (!inited) {
        cudaStreamCreateWithFlags(&s1, cudaStreamNonBlocking);
        cudaStreamCreateWithFlags(&s2, cudaStreamNonBlocking);
        cudaStreamCreateWithFlags(&s3, cudaStreamNonBlocking);
        cudaEventCreateWithFlags(&evRoot, cudaEventDisableTiming);
        cudaEventCreateWithFlags(&evA, cudaEventDisableTiming);
        cudaEventCreateWithFlags(&evB, cudaEventDisableTiming);
        cudaEventCreateWithFlags(&evC, cudaEventDisableTiming);
        cudaEventCreateWithFlags(&evF, cudaEventDisableTiming);
        cudaEventCreateWithFlags(&evY, cudaEventDisableTiming);
        cudaFuncSetAttribute(k_bil_mma, cudaFuncAttributeMaxDynamicSharedMemorySize, BIL_SMEM);
        inited = 1;
    }

    cudaEventRecord(evRoot, 0);
    cudaStreamWaitEvent(s1, evRoot, 0);
    cudaStreamWaitEvent(s2, evRoot, 0);
    cudaStreamWaitEvent(s3, evRoot, 0);

    k_ent_att<<<NN*EE*HH, 256>>>(att, mpos);                    // 1 (main)
    k_ht_att<<<RR, 256>>>(hts);                                 // 2 (main)
    k_seqf<<<dim3(64, 4), 256, 0, s2>>>(seq);                   // 3 (s2)
    cudaEventRecord(evC, s2);
    cudaStreamWaitEvent(0, evC, 0);
    k_rs_mma<<<dim3(12, 32), 256>>>();                          // 4 (main) <- profiled
    k_wht<<<dim3(96, 2), 256, 0, s2>>>(W_head, W_tail);         // 5 (s2)
    cudaEventRecord(evB, s2);
    k_ent_emb<<<dim3(NN*EE, 2), 256, 0, s3>>>(seq, mpos);       // 6 (s3)
    cudaStreamWaitEvent(s3, evB, 0);
    k_y1<<<dim3(12, 4, 2), 256, 0, s3>>>();                     // 7 (s3)
    cudaEventRecord(evY, s3);
    cudaStreamWaitEvent(0, evB, 0);
    cudaStreamWaitEvent(0, evY, 0);
    k_ht2<<<dim3(12, 32, 2), 256>>>(b_head, b_tail, hts);       // 8 (main)
    k_wt<<<3072, 128, 0, s1>>>(W_bil);                          // 9 (s1)
    cudaEventRecord(evA, s1);
    k_init_out<<<(RR*NOUT + 255)/256, 256, 0, s3>>>(b_bil, out);// 10 (s3)
    cudaEventRecord(evF, s3);
    cudaStreamWaitEvent(0, evA, 0);
    cudaStreamWaitEvent(0, evF, 0);
    k_bil_mma<<<dim3(KBL*4, RR/64), 128, BIL_SMEM>>>(out);      // 11 (main)
}

// round 17
// speedup vs baseline: 1.2073x; 1.0106x over previous
#include <cuda_runtime.h>
#include <math.h>

// ---------------- fixed problem shapes ----------------
#define NN   4
#define CC   1024
#define DD   768
#define HH   12
#define EE   32
#define MM   4
#define PP   256
#define RR   (NN*PP)     // 1024
#define KBL  12
#define NOUT 97

#define WSCALE     1024.0f
#define WSCALE_INV (1.0f/1024.0f)

// ---------------- scratch ----------------
__device__ float g_ent_emb[NN*EE*DD];
__device__ float g_ent_att[NN*EE*HH*CC];
__device__ float g_hs2    [RR*DD];
__device__ float g_ts2    [RR*DD];
__device__ float g_y1     [2*NN*EE*DD];

// fragment-packed A operands (split fp16, pair_slot layout, 16 u32 / row / kstep)
__device__ __align__(16) unsigned g_htaf[RR*64*16];   // ht_att x1024, 4 MB
__device__ __align__(16) unsigned g_rsf [RR*48*16];   // rs (unscaled), 3 MB

// W_bil fragments (fp16, x1024)
__device__ __align__(16) unsigned char g_Wp[3072UL*13*32*8];
// W_head/W_tail fragments: [2][96 kc][96 nt][32] uint2
__device__ __align__(16) unsigned char g_Whtp[2UL*96*96*32*8];
// seq fragments: [4][64 kc][96 nt][32] uint2
__device__ __align__(16) unsigned char g_seqf[4UL*64*96*32*8];

// ---------------- fp16 helpers ----------------
__device__ __forceinline__ unsigned pack_f16x2(float hi_f, float lo_f) {
    unsigned r;
    asm("cvt.rn.f16x2.f32 %0, %1, %2;" : "=r"(r) : "f"(hi_f), "f"(lo_f));
    return r;
}
__device__ __forceinline__ void split2h(float p0, float p1, unsigned& hi, unsigned& lo) {
    hi = pack_f16x2(p1, p0);
    float f0, f1;
    asm("{\n\t.reg .b16 h0, h1;\n\t"
        "mov.b32 {h0, h1}, %2;\n\t"
        "cvt.f32.f16 %0, h0;\n\t"
        "cvt.f32.f16 %1, h1;\n\t}"
        : "=f"(f0), "=f"(f1) : "r"(hi));
    lo = pack_f16x2(p1 - f1, p0 - f0);
}
__device__ __forceinline__ void mma_f16(float* d, const unsigned* a,
                                        unsigned b0, unsigned b1) {
    asm volatile(
        "mma.sync.aligned.m16n8k16.row.col.f32.f16.f16.f32 "
        "{%0,%1,%2,%3}, {%4,%5,%6,%7}, {%8,%9}, {%0,%1,%2,%3};"
        : "+f"(d[0]), "+f"(d[1]), "+f"(d[2]), "+f"(d[3])
        : "r"(a[0]), "r"(a[1]), "r"(a[2]), "r"(a[3]), "r"(b0), "r"(b1));
}
__device__ __forceinline__ int pair_slot(int p) {
    return (p < 4) ? 4*p : 4*(p - 4) + 1;
}
__device__ __forceinline__ void stage_pairs(unsigned* dst_row, int quad, float4 v) {
    unsigned hi0, lo0, hi1, lo1;
    split2h(v.x, v.y, hi0, lo0);
    split2h(v.z, v.w, hi1, lo1);
    int p0 = quad*2, p1 = p0 + 1;
    int s0 = pair_slot(p0), s1 = pair_slot(p1);
    dst_row[s0] = hi0; dst_row[s0 + 2] = lo0;
    dst_row[s1] = hi1; dst_row[s1 + 2] = lo1;
}

// ============================================================================
// P0: pack W_bil. grid 3072, 128 thr
// ============================================================================
__global__ void k_wt(const float* __restrict__ Wb) {
    __shared__ float Wsm[16*104];
    int chunk = blockIdx.x;
    int tid = threadIdx.x;
    int row0 = chunk * 16;

    for (int idx = tid; idx < 16*104; idx += 128) {
        int r = idx / 104, n = idx - r*104;
        Wsm[idx] = (n < NOUT) ? Wb[(size_t)(row0 + r)*NOUT + n] * WSCALE : 0.0f;
    }
    __syncthreads();

    for (int e = tid; e < 13*32; e += 128) {
        int nt = e >> 5, lane = e & 31;
        int g = lane >> 2, t = lane & 3;
        int n = nt*8 + g, k0 = 2*t;
        unsigned b0 = pack_f16x2(Wsm[(k0 + 1)*104 + n], Wsm[(k0    )*104 + n]);
        unsigned b1 = pack_f16x2(Wsm[(k0 + 9)*104 + n], Wsm[(k0 + 8)*104 + n]);
        *(uint2*)(g_Wp + ((size_t)(chunk*13 + nt)*32 + lane)*8) = make_uint2(b0, b1);
    }
}

// ============================================================================
// P1: pack W_head / W_tail. grid (96, 2), 256 thr
// ============================================================================
__global__ void k_wht(const float* __restrict__ Wh, const float* __restrict__ Wt) {
    __shared__ float S[16*768];
    int kc = blockIdx.x;
    int w  = blockIdx.y;
    const float* W = w ? Wt : Wh;
    int tid = threadIdx.x;

    for (int idx = tid; idx < 16*768; idx += 256)
        S[idx] = W[(size_t)kc*16*768 + idx] * WSCALE;
    __syncthreads();

    for (int e = tid; e < 96*32; e += 256) {
        int nt = e >> 5, lane = e & 31;
        int g = lane >> 2, t = lane & 3;
        int n = nt*8 + g, k0 = 2*t;
        unsigned b0 = pack_f16x2(S[(k0 + 1)*768 + n], S[(k0    )*768 + n]);
        unsigned b1 = pack_f16x2(S[(k0 + 9)*768 + n], S[(k0 + 8)*768 + n]);
        *(uint2*)(g_Whtp + ((((size_t)w*96 + kc)*96 + nt)*32 + lane)*8) = make_uint2(b0, b1);
    }
}

// ============================================================================
// P2: pack seq. grid (64, 4), 256 thr
// ============================================================================
__global__ void k_seqf(const float* __restrict__ seq) {
    __shared__ float S[16*768];
    int kc = blockIdx.x;
    int b  = blockIdx.y;
    int tid = threadIdx.x;

    for (int idx = tid; idx < 16*768; idx += 256)
        S[idx] = seq[((size_t)b*CC + kc*16)*768 + idx];
    __syncthreads();

    for (int e = tid; e < 96*32; e += 256) {
        int nt = e >> 5, lane = e & 31;
        int g = lane >> 2, t = lane & 3;
        int n = nt*8 + g, k0 = 2*t;
        unsigned b0 = pack_f16x2(S[(k0 + 1)*768 + n], S[(k0    )*768 + n]);
        unsigned b1 = pack_f16x2(S[(k0 + 9)*768 + n], S[(k0 + 8)*768 + n]);
        *(uint2*)(g_seqf + ((((size_t)b*64 + kc)*96 + nt)*32 + lane)*8) = make_uint2(b0, b1);
    }
}

// ============================================================================
// K1: entity embeddings = logsumexp. grid (128, 2)
// ============================================================================
__global__ void k_ent_emb(const float* __restrict__ seq,
                          const int*   __restrict__ mpos) {
    int be = blockIdx.x;
    int half = blockIdx.y;
    int b  = be / EE;
    const int* mp = mpos + be*MM;
    int p0 = mp[0], p1 = mp[1], p2 = mp[2], p3 = mp[3];
    const float* sb = seq + (long)b*CC*DD;
    int d0 = half*(DD/2), d1 = d0 + DD/2;
    for (int dd = d0 + threadIdx.x; dd < d1; dd += blockDim.x) {
        float v0 = sb[p0*DD+dd], v1 = sb[p1*DD+dd];
        float v2 = sb[p2*DD+dd], v3 = sb[p3*DD+dd];
        float mx = fmaxf(fmaxf(v0, v1), fmaxf(v2, v3));
        float s  = expf(v0-mx) + expf(v1-mx) + expf(v2-mx) + expf(v3-mx);
        g_ent_emb[be*DD + dd] = mx + logf(s);
    }
}

// ============================================================================
// K2: entity attention = mean over mention attention rows
// ============================================================================
__global__ void k_ent_att(const float* __restrict__ att,
                          const int*   __restrict__ mpos) {
    int id = blockIdx.x;
    int hd = id % HH;
    int be = id / HH;
    int b  = be / EE;
    const int* mp = mpos + be*MM;
    const float* ab = att + (long)(b*HH + hd)*CC*CC;
    float* ob = g_ent_att + (long)id*CC;
    int q0 = mp[0]*CC, q1 = mp[1]*CC, q2 = mp[2]*CC, q3 = mp[3]*CC;
    for (int c = threadIdx.x; c < CC; c += blockDim.x) {
        float s = ab[q0+c] + ab[q1+c] + ab[q2+c] + ab[q3+c];
        ob[c] = s * 0.25f;
    }
}

// ============================================================================
// K3: ht_att -> A-FRAGMENTS (x1024, split fp16). grid RR, 256 thr.
// ============================================================================
__global__ void k_ht_att(const int* __restrict__ hts) {
    int bp = blockIdx.x;
    int b  = bp / PP;
    int eh = hts[bp*2 + 0];
    int et = hts[bp*2 + 1];
    const float* ah = g_ent_att + (long)(b*EE + eh)*HH*CC;
    const float* at = g_ent_att + (long)(b*EE + et)*HH*CC;
    int tid = threadIdx.x;

    float v[4];
    float lsum = 0.f;
    #pragma unroll
    for (int q = 0; q < 2; q++) {
        int c0 = q*512 + 2*tid;
        #pragma unroll
        for (int j = 0; j < 2; j++) {
            int c = c0 + j;
            float s = 0.f;
            #pragma unroll
            for (int hd = 0; hd < HH; hd++)
                s += ah[hd*CC + c] * at[hd*CC + c];
            v[q*2 + j] = s * (1.0f / HH);
            lsum += s * (1.0f / HH);
        }
    }
    __shared__ float red[256];
    red[tid] = lsum;
    __syncthreads();
    for (int st = 128; st > 0; st >>= 1) {
        if (tid < st) red[tid] += red[tid + st];
        __syncthreads();
    }
    float scl = WSCALE / (red[0] + 1e-30f);

    unsigned* base = g_htaf + (size_t)bp*64*16;
    #pragma unroll
    for (int q = 0; q < 2; q++) {
        int p  = q*256 + tid;
        int ks = p >> 3, pl = p & 7;
        int slot = pair_slot(pl);
        unsigned hi, lo;
        split2h(v[q*2]*scl, v[q*2 + 1]*scl, hi, lo);
        base[ks*16 + slot]     = hi;
        base[ks*16 + slot + 2] = lo;
    }
}

// ============================================================================
// K4: rs = ht_att @ seq. A/B from global fragments; k-loop block-batched x4
// for MLP (~24 loads in flight). grid (12, 32), 256 thr, K-split x2.
// ============================================================================
__global__ void __launch_bounds__(256, 2) k_rs_mma() {
    __shared__ __align__(16) float Xch[128*16];

    int ntg0 = blockIdx.x * 8;
    int r0   = blockIdx.y * 32;
    int b    = r0 >> 8;
    int tid = threadIdx.x;
    int kh  = tid >> 7;
    int st  = tid & 127;
    int wid = st >> 5, lane = st & 31;
    int g = lane >> 2, t = lane & 3;

    const unsigned* Af0 = g_htaf + ((size_t)(r0 + g     )*64 + kh*32)*16 + 4*t;
    const unsigned* Af1 = Af0 + (size_t) 8*64*16;
    const unsigned* Af2 = Af0 + (size_t)16*64*16;
    const unsigned* Af3 = Af0 + (size_t)24*64*16;

    const size_t KSTR = (size_t)96*256;
    const char* Bp0 = (const char*)g_seqf + (((size_t)b*64*96) + ntg0 + wid*2    )*256 + lane*8 + (size_t)(kh*32)*KSTR;
    const char* Bp1 = (const char*)g_seqf + (((size_t)b*64*96) + ntg0 + wid*2 + 1)*256 + lane*8 + (size_t)(kh*32)*KSTR;

    float acc[2][2][4];
    #pragma unroll
    for (int a = 0; a < 2; a++)
        #pragma unroll
        for (int n = 0; n < 2; n++)
            #pragma unroll
            for (int c = 0; c < 4; c++) acc[a][n][c] = 0.0f;

    const int NKH = 32;
    for (int blk = 0; blk < NKH; blk += 4) {
        uint4 va[4], vb[4], vc[4], vd[4];
        uint2 w0[4], w1[4];
        #pragma unroll
        for (int u = 0; u < 4; u++) {
            int ks = blk + u;
            va[u] = *(const uint4*)(Af0 + ks*16);
            vb[u] = *(const uint4*)(Af1 + ks*16);
            vc[u] = *(const uint4*)(Af2 + ks*16);
            vd[u] = *(const uint4*)(Af3 + ks*16);
            w0[u] = *(const uint2*)(Bp0 + (size_t)ks*KSTR);
            w1[u] = *(const uint2*)(Bp1 + (size_t)ks*KSTR);
        }
        #pragma unroll
        for (int u = 0; u < 4; u++) {
            unsigned ahi0[4] = {va[u].x, vb[u].x, va[u].y, vb[u].y};
            unsigned alo0[4] = {va[u].z, vb[u].z, va[u].w, vb[u].w};
            unsigned ahi1[4] = {vc[u].x, vd[u].x, vc[u].y, vd[u].y};
            unsigned alo1[4] = {vc[u].z, vd[u].z, vc[u].w, vd[u].w};
            mma_f16(acc[0][0], ahi0, w0[u].x, w0[u].y);
            mma_f16(acc[0][0], alo0, w0[u].x, w0[u].y);
            mma_f16(acc[0][1], ahi0, w1[u].x, w1[u].y);
            mma_f16(acc[0][1], alo0, w1[u].x, w1[u].y);
            mma_f16(acc[1][0], ahi1, w0[u].x, w0[u].y);
            mma_f16(acc[1][0], alo1, w0[u].x, w0[u].y);
            mma_f16(acc[1][1], ahi1, w1[u].x, w1[u].y);
            mma_f16(acc[1][1], alo1, w1[u].x, w1[u].y);
        }
    }

    if (kh == 1) {
        #pragma unroll
        for (int af = 0; af < 2; af++)
            #pragma unroll
            for (int nt = 0; nt < 2; nt++)
                *(float4*)&Xch[st*16 + af*8 + nt*4] =
                    make_float4(acc[af][nt][0], acc[af][nt][1], acc[af][nt][2], acc[af][nt][3]);
    }
    __syncthreads();
    if (kh == 0) {
        #pragma unroll
        for (int af = 0; af < 2; af++) {
            int ra = r0 + af*16 + g;
            #pragma unroll
            for (int nt = 0; nt < 2; nt++) {
                float4 o = *(const float4*)&Xch[st*16 + af*8 + nt*4];
                int p  = (ntg0 + wid*2 + nt)*4 + t;
                int ks = p >> 3, slot = pair_slot(p & 7);
                float va0 = (acc[af][nt][0] + o.x)*WSCALE_INV;
                float va1 = (acc[af][nt][1] + o.y)*WSCALE_INV;
                float vb0 = (acc[af][nt][2] + o.z)*WSCALE_INV;
                float vb1 = (acc[af][nt][3] + o.w)*WSCALE_INV;
                unsigned hi, lo;
                split2h(va0, va1, hi, lo);
                unsigned* da = g_rsf + ((size_t)ra*48 + ks)*16;
                da[slot] = hi; da[slot + 2] = lo;
                split2h(vb0, vb1, hi, lo);
                unsigned* db = g_rsf + ((size_t)(ra + 8)*48 + ks)*16;
                db[slot] = hi; db[slot + 2] = lo;
            }
        }
    }
}

// ============================================================================
// K5a: Y1 = ent_emb @ W_top (128 rows, K=768). grid (12, 4, 2), 256 thr.
// ============================================================================
#define APITCH 20
__global__ void __launch_bounds__(256) k_y1() {
    __shared__ __align__(16) unsigned As[2][2][32*APITCH];
    __shared__ __align__(16) float Xch[128*16];

    int ntg0 = blockIdx.x * 8;
    int r0   = blockIdx.y * 32;
    int col  = blockIdx.z;
    int tid = threadIdx.x;
    int kh  = tid >> 7;
    int st  = tid & 127;
    int wid = st >> 5, lane = st & 31;
    int g = lane >> 2, t = lane & 3;
    int arow = st >> 2, quad = st & 3;

    const float* Arow = g_ent_emb + (size_t)(r0 + arow)*DD + kh*384 + quad*4;
    const size_t KSTR = (size_t)96*256;
    const char* Bp0 = (const char*)g_Whtp + (((size_t)col*96*96) + ntg0 + wid*2    )*256 + lane*8 + (size_t)(kh*24)*KSTR;
    const char* Bp1 = (const char*)g_Whtp + (((size_t)col*96*96) + ntg0 + wid*2 + 1)*256 + lane*8 + (size_t)(kh*24)*KSTR;

    unsigned (*A)[32*APITCH] = As[kh];

    float4 pa = *(const float4*)(Arow);
    uint2 bc0 = *(const uint2*)(Bp0);
    uint2 bc1 = *(const uint2*)(Bp1);
    stage_pairs(&A[0][arow*APITCH], quad, pa);
    __syncthreads();

    float acc[2][2][4];
    #pragma unroll
    for (int a = 0; a < 2; a++)
        #pragma unroll
        for (int n = 0; n < 2; n++)
            #pragma unroll
            for (int c = 0; c < 4; c++) acc[a][n][c] = 0.0f;

    const int NKH = 24;
    uint2 pb0, pb1;
    for (int ks = 0; ks < NKH; ks++) {
        int s = ks & 1;
        if (ks + 1 < NKH) {
            pa = *(const float4*)(Arow + (ks + 1)*16);
            pb0 = *(const uint2*)(Bp0 + (size_t)(ks + 1)*KSTR);
            pb1 = *(const uint2*)(Bp1 + (size_t)(ks + 1)*KSTR);
        }
        #pragma unroll
        for (int af = 0; af < 2; af++) {
            int ra = af*16 + g, rb = ra + 8;
            uint4 ua = *(const uint4*)&A[s][ra*APITCH + 4*t];
            uint4 ub = *(const uint4*)&A[s][rb*APITCH + 4*t];
            unsigned ahi[4] = {ua.x, ub.x, ua.y, ub.y};
            unsigned alo[4] = {ua.z, ub.z, ua.w, ub.w};
            mma_f16(acc[af][0], ahi, bc0.x, bc0.y);
            mma_f16(acc[af][0], alo, bc0.x, bc0.y);
            mma_f16(acc[af][1], ahi, bc1.x, bc1.y);
            mma_f16(acc[af][1], alo, bc1.x, bc1.y);
        }
        if (ks + 1 < NKH) {
            stage_pairs(&A[s^1][arow*APITCH], quad, pa);
            bc0 = pb0; bc1 = pb1;
        }
        __syncthreads();
    }

    if (kh == 1) {
        #pragma unroll
        for (int af = 0; af < 2; af++)
            #pragma unroll
            for (int nt = 0; nt < 2; nt++)
                *(float4*)&Xch[st*16 + af*8 + nt*4] =
                    make_float4(acc[af][nt][0], acc[af][nt][1], acc[af][nt][2], acc[af][nt][3]);
    }
    __syncthreads();
    if (kh == 0) {
        float* Y = g_y1 + (size_t)col*NN*EE*DD;
        #pragma unroll
        for (int af = 0; af < 2; af++) {
            int ra = r0 + af*16 + g;
            #pragma unroll
            for (int nt = 0; nt < 2; nt++) {
                float4 o = *(const float4*)&Xch[st*16 + af*8 + nt*4];
                int n0 = (ntg0 + wid*2 + nt)*8 + 2*t;
                *(float2*)(Y + (size_t)ra*DD + n0) =
                    make_float2((acc[af][nt][0] + o.x)*WSCALE_INV, (acc[af][nt][1] + o.y)*WSCALE_INV);
                *(float2*)(Y + (size_t)(ra+8)*DD + n0) =
                    make_float2((acc[af][nt][2] + o.z)*WSCALE_INV, (acc[af][nt][3] + o.w)*WSCALE_INV);
            }
        }
    }
}

// ============================================================================
// K5b: hs2/ts2 = tanh(rs @ W_bot + Y1[ent] + bias). Block-batched x4.
// grid (12, 32, 2), 256 thr.
// ============================================================================
__global__ void __launch_bounds__(256, 2) k_ht2(const float* __restrict__ bh,
                                                const float* __restrict__ bt,
                                                const int* __restrict__ hts) {
    __shared__ __align__(16) float Xch[128*16];
    __shared__ int eIdx[32];

    int ntg0 = blockIdx.x * 8;
    int r0   = blockIdx.y * 32;
    int col  = blockIdx.z;
    const float* bias = col ? bt : bh;
    float* outm = col ? g_ts2 : g_hs2;

    int tid = threadIdx.x;
    int kh  = tid >> 7;
    int st  = tid & 127;
    int wid = st >> 5, lane = st & 31;
    int g = lane >> 2, t = lane & 3;

    if (tid < 32) {
        int r = r0 + tid;
        eIdx[tid] = (r >> 8)*EE + hts[r*2 + col];
    }

    const unsigned* Af0 = g_rsf + ((size_t)(r0 + g     )*48 + kh*24)*16 + 4*t;
    const unsigned* Af1 = Af0 + (size_t) 8*48*16;
    const unsigned* Af2 = Af0 + (size_t)16*48*16;
    const unsigned* Af3 = Af0 + (size_t)24*48*16;

    const size_t KSTR = (size_t)96*256;
    const char* Bp0 = (const char*)g_Whtp + (((size_t)col*96*96) + ntg0 + wid*2    )*256 + lane*8 + (size_t)(48 + kh*24)*KSTR;
    const char* Bp1 = (const char*)g_Whtp + (((size_t)col*96*96) + ntg0 + wid*2 + 1)*256 + lane*8 + (size_t)(48 + kh*24)*KSTR;

    float acc[2][2][4];
    #pragma unroll
    for (int a = 0; a < 2; a++)
        #pragma unroll
        for (int n = 0; n < 2; n++)
            #pragma unroll
            for (int c = 0; c < 4; c++) acc[a][n][c] = 0.0f;

    const int NKH = 24;
    for (int blk = 0; blk < NKH; blk += 4) {
        uint4 va[4], vb[4], vc[4], vd[4];
        uint2 w0[4], w1[4];
        #pragma unroll
        for (int u = 0; u < 4; u++) {
            int ks = blk + u;
            va[u] = *(const uint4*)(Af0 + ks*16);
            vb[u] = *(const uint4*)(Af1 + ks*16);
            vc[u] = *(const uint4*)(Af2 + ks*16);
            vd[u] = *(const uint4*)(Af3 + ks*16);
            w0[u] = *(const uint2*)(Bp0 + (size_t)ks*KSTR);
            w1[u] = *(const uint2*)(Bp1 + (size_t)ks*KSTR);
        }
        #pragma unroll
        for (int u = 0; u < 4; u++) {
            unsigned ahi0[4] = {va[u].x, vb[u].x, va[u].y, vb[u].y};
            unsigned alo0[4] = {va[u].z, vb[u].z, va[u].w, vb[u].w};
            unsigned ahi1[4] = {vc[u].x, vd[u].x, vc[u].y, vd[u].y};
            unsigned alo1[4] = {vc[u].z, vd[u].z, vc[u].w, vd[u].w};
            mma_f16(acc[0][0], ahi0, w0[u].x, w0[u].y);
            mma_f16(acc[0][0], alo0, w0[u].x, w0[u].y);
            mma_f16(acc[0][1], ahi0, w1[u].x, w1[u].y);
            mma_f16(acc[0][1], alo0, w1[u].x, w1[u].y);
            mma_f16(acc[1][0], ahi1, w0[u].x, w0[u].y);
            mma_f16(acc[1][0], alo1, w0[u].x, w0[u].y);
            mma_f16(acc[1][1], ahi1, w1[u].x, w1[u].y);
            mma_f16(acc[1][1], alo1, w1[u].x, w1[u].y);
        }
    }

    if (kh == 1) {
        #pragma unroll
        for (int af = 0; af < 2; af++)
            #pragma unroll
            for (int nt = 0; nt < 2; nt++)
                *(float4*)&Xch[st*16 + af*8 + nt*4] =
                    make_float4(acc[af][nt][0], acc[af][nt][1], acc[af][nt][2], acc[af][nt][3]);
    }
    __syncthreads();
    if (kh == 0) {
        const float* Y = g_y1 + (size_t)col*NN*EE*DD;
        #pragma unroll
        for (int af = 0; af < 2; af++) {
            int lrow = af*16 + g;
            int ra = r0 + lrow;
            const float* Ya = Y + (size_t)eIdx[lrow]*DD;
            const float* Yb = Y + (size_t)eIdx[lrow + 8]*DD;
            #pragma unroll
            for (int nt = 0; nt < 2; nt++) {
                float4 o = *(const float4*)&Xch[st*16 + af*8 + nt*4];
                int n0 = (ntg0 + wid*2 + nt)*8 + 2*t;
                float2 ya = *(const float2*)(Ya + n0);
                float2 yb = *(const float2*)(Yb + n0);
                float b0v = bias[n0], b1v = bias[n0 + 1];
                *(float2*)(outm + (size_t)ra*DD + n0) =
                    make_float2(tanhf((acc[af][nt][0] + o.x)*WSCALE_INV + ya.x + b0v),
                                tanhf((acc[af][nt][1] + o.y)*WSCALE_INV + ya.y + b1v));
                *(float2*)(outm + (size_t)(ra+8)*DD + n0) =
                    make_float2(tanhf((acc[af][nt][2] + o.z)*WSCALE_INV + yb.x + b0v),
                                tanhf((acc[af][nt][3] + o.w)*WSCALE_INV + yb.y + b1v));
            }
        }
    }
}

// ============================================================================
// K6: init output with bias
// ============================================================================
__global__ void k_init_out(const float* __restrict__ b_bil, float* __restrict__ out) {
    int i = blockIdx.x*256 + threadIdx.x;
    if (i < RR*NOUT) out[i] = b_bil[i % NOUT];
}

// ============================================================================
// K7: bilinear via fp16 single-term A mma (unchanged).
// ============================================================================
#define TS_OFF  0
#define HS_OFF  16896
#define WB_OFF  (HS_OFF + 64*17*4)
#define CHUNK_BYTES 3328
#define BIL_SMEM (WB_OFF + 2*CHUNK_BYTES)

__global__ void __launch_bounds__(128) k_bil_mma(float* __restrict__ out) {
    extern __shared__ __align__(16) char smem[];
    float* tsS = (float*)(smem + TS_OFF);
    float* hsS = (float*)(smem + HS_OFF);
    char*  Wbuf = smem + WB_OFF;

    const int kb = blockIdx.x >> 2;
    const int qt = blockIdx.x & 3;
    const int r0 = blockIdx.y * 64;
    const int tid  = threadIdx.x;
    const int wid  = tid >> 5;
    const int lane = tid & 31;
    const int g = lane >> 2, t = lane & 3;

    for (int idx = tid; idx < 64*64; idx += 128) {
        int rr = idx >> 6, j = idx & 63;
        tsS[rr*66 + j] = g_ts2[(size_t)(r0 + rr)*DD + kb*64 + j];
    }
    for (int idx = tid; idx < 64*16; idx += 128) {
        int rr = idx >> 4, ii = idx & 15;
        hsS[rr*17 + ii] = g_hs2[(size_t)(r0 + rr)*DD + kb*64 + qt*16 + ii];
    }
    const size_t chunk0 = (size_t)(kb*256 + qt*64);
    {
        const char* src = (const char*)g_Wp + chunk0*CHUNK_BYTES;
        for (int e = tid; e < 416; e += 128)
            *(uint2*)(Wbuf + e*8) = *(const uint2*)(src + e*8);
    }
    __syncthreads();

    float acc[13][4];
    #pragma unroll
    for (int n = 0; n < 13; n++)
        #pragma unroll
        for (int c = 0; c < 4; c++) acc[n][c] = 0.0f;

    for (int cc = 0; cc < 64; cc++) {
        int s = cc & 1;
        uint2 pw0, pw1, pw2, pw3;
        if (cc + 1 < 64) {
            const char* src = (const char*)g_Wp + (chunk0 + cc + 1)*CHUNK_BYTES;
            pw0 = *(const uint2*)(src + (tid      )*8);
            pw1 = *(const uint2*)(src + (tid + 128)*8);
            pw2 = *(const uint2*)(src + (tid + 256)*8);
            if (tid < 32) pw3 = *(const uint2*)(src + (tid + 384)*8);
        }

        int i_loc = cc >> 2;
        int j0    = (cc & 3) * 16;
        unsigned a[4];
        {
            int ra = wid*16 + g, rb = ra + 8;
            float hA = hsS[ra*17 + i_loc];
            float hB = hsS[rb*17 + i_loc];
            float2 tA0 = *(const float2*)&tsS[ra*66 + j0 + 2*t];
            float2 tA1 = *(const float2*)&tsS[ra*66 + j0 + 2*t + 8];
            float2 tB0 = *(const float2*)&tsS[rb*66 + j0 + 2*t];
            float2 tB1 = *(const float2*)&tsS[rb*66 + j0 + 2*t + 8];
            a[0] = pack_f16x2(hA*tA0.y, hA*tA0.x);
            a[1] = pack_f16x2(hB*tB0.y, hB*tB0.x);
            a[2] = pack_f16x2(hA*tA1.y, hA*tA1.x);
            a[3] = pack_f16x2(hB*tB1.y, hB*tB1.x);
        }

        #pragma unroll
        for (int nt = 0; nt < 13; nt++) {
            uint2 w = *(const uint2*)(Wbuf + s*CHUNK_BYTES + (nt*32 + lane)*8);
            mma_f16(acc[nt], a, w.x, w.y);
        }

        __syncthreads();
        if (cc + 1 < 64) {
            char* dst = Wbuf + (s^1)*CHUNK_BYTES;
            *(uint2*)(dst + (tid      )*8) = pw0;
            *(uint2*)(dst + (tid + 128)*8) = pw1;
            *(uint2*)(dst + (tid + 256)*8) = pw2;
            if (tid < 32) *(uint2*)(dst + (tid + 384)*8) = pw3;
        }
        __syncthreads();
    }

    {
        int r1 = r0 + wid*16 + g;
        #pragma unroll
        for (int nt = 0; nt < 13; nt++) {
            int n0 = nt*8 + 2*t;
            const float* av = acc[nt];
            if (n0 < NOUT) {
                atomicAdd(&out[(size_t)r1*NOUT + n0],     av[0]*WSCALE_INV);
                atomicAdd(&out[(size_t)(r1+8)*NOUT + n0], av[2]*WSCALE_INV);
            }
            if (n0 + 1 < NOUT) {
                atomicAdd(&out[(size_t)r1*NOUT + n0 + 1],     av[1]*WSCALE_INV);
                atomicAdd(&out[(size_t)(r1+8)*NOUT + n0 + 1], av[3]*WSCALE_INV);
            }
        }
    }
}

// ============================================================================
// launch: multi-stream DAG; k_rs_mma kept 4th for profiling.
// ============================================================================
extern "C" void kernel_launch(void* const* d_in, const int* in_sizes, int n_in,
                              void* d_out, int out_size) {
    const float* seq    = (const float*)d_in[0];
    const float* att    = (const float*)d_in[1];
    const int*   mpos   = (const int*  )d_in[2];
    const int*   hts    = (const int*  )d_in[3];
    const float* W_head = (const float*)d_in[4];
    const float* b_head = (const float*)d_in[5];
    const float* W_tail = (const float*)d_in[6];
    const float* b_tail = (const float*)d_in[7];
    const float* W_bil  = (const float*)d_in[8];
    const float* b_bil  = (const float*)d_in[9];
    float* out = (float*)d_out;

    static cudaStream_t s1, s2, s3;
    static cudaEvent_t evRoot, evA, evB, evC, evF, evY;
    static int inited = 0;
    if (!inited) {
        cudaStreamCreateWithFlags(&s1, cudaStreamNonBlocking);
        cudaStreamCreateWithFlags(&s2, cudaStreamNonBlocking);
        cudaStreamCreateWithFlags(&s3, cudaStreamNonBlocking);
        cudaEventCreateWithFlags(&evRoot, cudaEventDisableTiming);
        cudaEventCreateWithFlags(&evA, cudaEventDisableTiming);
        cudaEventCreateWithFlags(&evB, cudaEventDisableTiming);
        cudaEventCreateWithFlags(&evC, cudaEventDisableTiming);
        cudaEventCreateWithFlags(&evF, cudaEventDisableTiming);
        cudaEventCreateWithFlags(&evY, cudaEventDisableTiming);
        cudaFuncSetAttribute(k_bil_mma, cudaFuncAttributeMaxDynamicSharedMemorySize, BIL_SMEM);
        inited = 1;
    }

    cudaEventRecord(evRoot, 0);
    cudaStreamWaitEvent(s1, evRoot, 0);
    cudaStreamWaitEvent(s2, evRoot, 0);
    cudaStreamWaitEvent(s3, evRoot, 0);

    k_ent_att<<<NN*EE*HH, 256>>>(att, mpos);                    // 1 (main)
    k_ht_att<<<RR, 256>>>(hts);                                 // 2 (main)
    k_seqf<<<dim3(64, 4), 256, 0, s2>>>(seq);                   // 3 (s2)
    cudaEventRecord(evC, s2);
    cudaStreamWaitEvent(0, evC, 0);
    k_rs_mma<<<dim3(12, 32), 256>>>();                          // 4 (main) <- profiled
    k_wht<<<dim3(96, 2), 256, 0, s2>>>(W_head, W_tail);         // 5 (s2)
    cudaEventRecord(evB, s2);
    k_ent_emb<<<dim3(NN*EE, 2), 256, 0, s3>>>(seq, mpos);       // 6 (s3)
    cudaStreamWaitEvent(s3, evB, 0);
    k_y1<<<dim3(12, 4, 2), 256, 0, s3>>>();                     // 7 (s3)
    cudaEventRecord(evY, s3);
    cudaStreamWaitEvent(0, evB, 0);
    cudaStreamWaitEvent(0, evY, 0);
    k_ht2<<<dim3(12, 32, 2), 256>>>(b_head, b_tail, hts);       // 8 (main)
    k_wt<<<3072, 128, 0, s1>>>(W_bil);                          // 9 (s1)
    cudaEventRecord(evA, s1);
    k_init_out<<<(RR*NOUT + 255)/256, 256, 0, s3>>>(b_bil, out);// 10 (s3)
    cudaEventRecord(evF, s3);
    cudaStreamWaitEvent(0, evA, 0);
    cudaStreamWaitEvent(0, evF, 0);
    k_bil_mma<<<dim3(KBL*4, RR/64), 128, BIL_SMEM>>>(out);      // 11 (main)
}